// round 10
// baseline (speedup 1.0000x reference)
#include <cuda_runtime.h>
#include <cstdint>

#define T_STEPS 100
#define B 16
#define E 128
#define H 256
#define L 2048
#define CHAIN_BLOCKS 64

// ---------------- device scratch (static allocations only) ----------------
__device__ float g_enc_feat[B * L * H];                 // 33.5 MB
__device__ float g_WhT[512 * 256];
__device__ float g_WsT[512 * 256];
__device__ float g_WoutT[768 * 256];
__device__ float g_WihT[128 * 1024];
__device__ float g_WxT[128 * 128];
__device__ float g_x_all[T_STEPS * B * E];
__device__ float g_gi[T_STEPS * B * 4 * H];
__device__ float g_h_all[(T_STEPS + 1) * B * H];
__device__ float g_c_all[(T_STEPS + 1) * B * H];
__device__ float g_dec_all[T_STEPS * B * H];
__device__ float g_ctx_all[T_STEPS * B * 2 * H];
__device__ float g_e_tr[B * L * 128];                   // [b][l][t(pad128)]
__device__ volatile unsigned g_flags[CHAIN_BLOCKS];     // chain step flags

// ---------------- fast math helpers ----------------
__device__ __forceinline__ float tanh_f(float x) {
    float e = __expf(2.f * x);
    return 1.f - __fdividef(2.f, e + 1.f);
}
__device__ __forceinline__ float sig_f(float x) {
    return __fdividef(1.f, 1.f + __expf(-x));
}
__device__ __forceinline__ float ex2(float x) {
    float r;
    asm("ex2.approx.ftz.f32 %0, %1;" : "=f"(r) : "f"(x));
    return r;
}
__device__ __forceinline__ float rcp(float x) {
    float r;
    asm("rcp.approx.ftz.f32 %0, %1;" : "=f"(r) : "f"(x));
    return r;
}
__device__ __forceinline__ float wreduce(float s) {
    #pragma unroll
    for (int off = 16; off; off >>= 1) s += __shfl_xor_sync(0xffffffffu, s, off);
    return s;
}
__device__ __forceinline__ float wmax(float s) {
    #pragma unroll
    for (int off = 16; off; off >>= 1) s = fmaxf(s, __shfl_xor_sync(0xffffffffu, s, off));
    return s;
}
__device__ __forceinline__ unsigned long long pack2(float x, float y) {
    unsigned long long r;
    asm("mov.b64 %0, {%1, %2};" : "=l"(r) : "f"(x), "f"(y));
    return r;
}
__device__ __forceinline__ void fma2(unsigned long long& d, unsigned long long a, unsigned long long b) {
    asm("fma.rn.f32x2 %0, %1, %2, %3;" : "=l"(d) : "l"(a), "l"(b), "l"(d));
}
__device__ __forceinline__ float2 unpack2(unsigned long long v) {
    float2 f;
    asm("mov.b64 {%0, %1}, %2;" : "=f"(f.x), "=f"(f.y) : "l"(v));
    return f;
}

// ---------------- prep: all transposes + h/c init + flag reset -------------
__global__ void k_prep(const float* __restrict__ Wh, const float* __restrict__ Ws_,
                       const float* __restrict__ Wout, const float* __restrict__ Wih,
                       const float* __restrict__ Wx,
                       const float* __restrict__ h0, const float* __restrict__ c0) {
    int blk = blockIdx.x, tid = threadIdx.x;
    if (blk == 0 && tid < CHAIN_BLOCKS) g_flags[tid] = 0u;
    if (blk < 512) {
        int i = blk * 256 + tid;
        int j = i & 255, k = i >> 8;
        g_WhT[i] = Wh[j * 512 + k];
    } else if (blk < 1024) {
        int i = (blk - 512) * 256 + tid;
        int j = i & 255, k = i >> 8;
        g_WsT[i] = Ws_[j * 512 + k];
    } else if (blk < 1792) {
        int i = (blk - 1024) * 256 + tid;
        int j = i & 255, k = i >> 8;
        g_WoutT[i] = Wout[j * 768 + k];
    } else if (blk < 2304) {
        int i = (blk - 1792) * 256 + tid;
        int j = i & 1023, k = i >> 10;
        g_WihT[i] = Wih[j * 128 + k];
    } else if (blk < 2368) {
        int i = (blk - 2304) * 256 + tid;
        int j = i & 127, k = i >> 7;
        g_WxT[i] = Wx[j * (2 * H + E) + k];
    } else {
        int i = (blk - 2368) * 256 + tid;
        g_h_all[i] = h0[i];
        g_c_all[i] = c0[i];
    }
}

// ---------------- x GEMM: [1600,128] = dec_in @ WxT + bx -------------------
__global__ void __launch_bounds__(256)
k_xg(const float* __restrict__ Din, const float* __restrict__ bx) {
    __shared__ float As[64][17];
    __shared__ float Bs[16][64];
    const int m0 = blockIdx.y * 64;
    const int n0 = blockIdx.x * 64;
    const int tid = threadIdx.x;
    const int tx = tid & 15, ty = tid >> 4;
    float acc[4][4] = {};
    for (int k0 = 0; k0 < 128; k0 += 16) {
        for (int i = tid; i < 64 * 16; i += 256) {
            int m = i >> 4, k = i & 15;
            As[m][k] = Din[(size_t)(m0 + m) * 128 + k0 + k];
        }
        for (int i = tid; i < 16 * 64; i += 256) {
            int k = i >> 6, n = i & 63;
            Bs[k][n] = g_WxT[(size_t)(k0 + k) * 128 + n0 + n];
        }
        __syncthreads();
        #pragma unroll
        for (int kk = 0; kk < 16; kk++) {
            float a0 = As[ty * 4 + 0][kk], a1 = As[ty * 4 + 1][kk];
            float a2 = As[ty * 4 + 2][kk], a3 = As[ty * 4 + 3][kk];
            float4 b4 = *(const float4*)&Bs[kk][tx * 4];
            acc[0][0] += a0 * b4.x; acc[0][1] += a0 * b4.y; acc[0][2] += a0 * b4.z; acc[0][3] += a0 * b4.w;
            acc[1][0] += a1 * b4.x; acc[1][1] += a1 * b4.y; acc[1][2] += a1 * b4.z; acc[1][3] += a1 * b4.w;
            acc[2][0] += a2 * b4.x; acc[2][1] += a2 * b4.y; acc[2][2] += a2 * b4.z; acc[2][3] += a2 * b4.w;
            acc[3][0] += a3 * b4.x; acc[3][1] += a3 * b4.y; acc[3][2] += a3 * b4.z; acc[3][3] += a3 * b4.w;
        }
        __syncthreads();
    }
    #pragma unroll
    for (int i = 0; i < 4; i++) {
        int r = m0 + ty * 4 + i;
        #pragma unroll
        for (int j = 0; j < 4; j++) {
            int n = n0 + tx * 4 + j;
            g_x_all[(size_t)r * 128 + n] = acc[i][j] + bx[n];
        }
    }
}

// ---------------- gi GEMM: [1600,1024] = x_all @ WihT + bih + bhh ----------
__global__ void __launch_bounds__(256)
k_gig(const float* __restrict__ bih, const float* __restrict__ bhh) {
    __shared__ float As[64][17];
    __shared__ float Bs[16][64];
    const int m0 = blockIdx.y * 64;
    const int n0 = blockIdx.x * 64;
    const int tid = threadIdx.x;
    const int tx = tid & 15, ty = tid >> 4;
    float acc[4][4] = {};
    for (int k0 = 0; k0 < 128; k0 += 16) {
        for (int i = tid; i < 64 * 16; i += 256) {
            int m = i >> 4, k = i & 15;
            As[m][k] = g_x_all[(size_t)(m0 + m) * 128 + k0 + k];
        }
        for (int i = tid; i < 16 * 64; i += 256) {
            int k = i >> 6, n = i & 63;
            Bs[k][n] = g_WihT[(size_t)(k0 + k) * 1024 + n0 + n];
        }
        __syncthreads();
        #pragma unroll
        for (int kk = 0; kk < 16; kk++) {
            float a0 = As[ty * 4 + 0][kk], a1 = As[ty * 4 + 1][kk];
            float a2 = As[ty * 4 + 2][kk], a3 = As[ty * 4 + 3][kk];
            float4 b4 = *(const float4*)&Bs[kk][tx * 4];
            acc[0][0] += a0 * b4.x; acc[0][1] += a0 * b4.y; acc[0][2] += a0 * b4.z; acc[0][3] += a0 * b4.w;
            acc[1][0] += a1 * b4.x; acc[1][1] += a1 * b4.y; acc[1][2] += a1 * b4.z; acc[1][3] += a1 * b4.w;
            acc[2][0] += a2 * b4.x; acc[2][1] += a2 * b4.y; acc[2][2] += a2 * b4.z; acc[2][3] += a2 * b4.w;
            acc[3][0] += a3 * b4.x; acc[3][1] += a3 * b4.y; acc[3][2] += a3 * b4.z; acc[3][3] += a3 * b4.w;
        }
        __syncthreads();
    }
    #pragma unroll
    for (int i = 0; i < 4; i++) {
        int r = m0 + ty * 4 + i;
        #pragma unroll
        for (int j = 0; j < 4; j++) {
            int n = n0 + tx * 4 + j;
            g_gi[(size_t)r * 1024 + n] = acc[i][j] + bih[n] + bhh[n];
        }
    }
}

// ================= FAT kernel: chain (blocks 0..63) ∥ encfeat (64..1087) ===
__global__ void __launch_bounds__(256)
k_fat(const float* __restrict__ Whh, const float* __restrict__ ES,
      const float* __restrict__ bh) {
    __shared__ __align__(16) float smem_u[4096];   // 16 KB union
    const int tid = threadIdx.x;

    if (blockIdx.x < CHAIN_BLOCKS) {
        // ---------------- persistent LSTM chain ----------------
        float* sh = smem_u;
        const int lane = tid & 31, wid = tid >> 5;
        const int gw = blockIdx.x * 8 + wid;
        const int j = gw >> 1;
        const int half = gw & 1;

        float w[4][8];
        #pragma unroll
        for (int g = 0; g < 4; g++)
            #pragma unroll
            for (int i = 0; i < 8; i++)
                w[g][i] = Whh[(size_t)(g * H + j) * H + lane + i * 32];

        float creg = 0.f;
        if (lane < 8) creg = g_c_all[(half * 8 + lane) * H + j];

        for (int t = 0; t < T_STEPS; t++) {
            {
                const float4* hsrc4 = (const float4*)(g_h_all + (size_t)t * B * H);
                float4* sh4 = (float4*)sh;
                #pragma unroll
                for (int i = 0; i < 4; i++) sh4[tid + i * 256] = __ldcg(hsrc4 + tid + i * 256);
            }
            __syncthreads();

            float gi0 = 0.f, gi1 = 0.f, gi2 = 0.f, gi3 = 0.f;
            if (lane < 8) {
                const float* gi = g_gi + (size_t)(t * B + half * 8 + lane) * 4 * H;
                gi0 = gi[j]; gi1 = gi[H + j]; gi2 = gi[2 * H + j]; gi3 = gi[3 * H + j];
            }

            float acc[4];
            #pragma unroll 2
            for (int i8 = 0; i8 < 8; i8++) {
                const float* hb = sh + (half * 8 + i8) * H;
                #pragma unroll
                for (int g = 0; g < 4; g++) {
                    float s = 0.f;
                    #pragma unroll
                    for (int i = 0; i < 8; i++) s += w[g][i] * hb[lane + i * 32];
                    acc[g] = wreduce(s);
                }
                if (lane == i8) {
                    float ig = acc[0] + gi0;
                    float fg = acc[1] + gi1;
                    float gg = acc[2] + gi2;
                    float og = acc[3] + gi3;
                    float cn = sig_f(fg) * creg + sig_f(ig) * tanh_f(gg);
                    float hn = sig_f(og) * tanh_f(cn);
                    creg = cn;
                    int bb = half * 8 + i8;
                    g_c_all[(size_t)(t + 1) * B * H + bb * H + j] = cn;
                    g_h_all[(size_t)(t + 1) * B * H + bb * H + j] = hn;
                }
            }

            // ---- flag-array grid barrier: no atomics, per-block slots ----
            __syncthreads();
            if (wid == 0) {
                if (lane == 0) {
                    __threadfence();
                    g_flags[blockIdx.x] = (unsigned)(t + 1);
                }
                unsigned m;
                do {
                    unsigned a = g_flags[lane];
                    unsigned b = g_flags[32 + lane];
                    m = a < b ? a : b;
                    #pragma unroll
                    for (int off = 16; off; off >>= 1) {
                        unsigned o = __shfl_xor_sync(0xffffffffu, m, off);
                        m = m < o ? m : o;
                    }
                } while (m < (unsigned)(t + 1));
                __threadfence();
            }
            __syncthreads();
        }
    } else {
        // ---------------- enc_feat GEMM tile ----------------
        float (*Ast)[132] = (float(*)[132])smem_u;
        float (*Bs)[64] = (float(*)[64])(smem_u + 2112);
        const int eb = blockIdx.x - CHAIN_BLOCKS;
        const int m0 = (eb >> 2) * 128;
        const int n0 = (eb & 3) * 64;
        const int tx = tid & 15, ty = tid >> 4;
        unsigned long long acc[4][4];
        #pragma unroll
        for (int p = 0; p < 4; p++)
            #pragma unroll
            for (int n = 0; n < 4; n++) acc[p][n] = 0ull;

        for (int k0 = 0; k0 < 512; k0 += 16) {
            __syncthreads();
            #pragma unroll
            for (int u = 0; u < 2; u++) {
                int idx = u * 256 + tid;
                int row = idx >> 2, q = idx & 3;
                float4 f = *(const float4*)(ES + (size_t)(m0 + row) * 512 + k0 + q * 4);
                Ast[q * 4 + 0][row] = f.x;
                Ast[q * 4 + 1][row] = f.y;
                Ast[q * 4 + 2][row] = f.z;
                Ast[q * 4 + 3][row] = f.w;
            }
            {
                int kk = tid >> 4, n4 = (tid & 15) * 4;
                *(float4*)&Bs[kk][n4] = *(const float4*)(g_WhT + (size_t)(k0 + kk) * 256 + n0 + n4);
            }
            __syncthreads();
            #pragma unroll
            for (int kk = 0; kk < 16; kk++) {
                unsigned long long a2[4];
                #pragma unroll
                for (int p = 0; p < 4; p++)
                    a2[p] = *(const unsigned long long*)&Ast[kk][ty * 8 + p * 2];
                float4 b4 = *(const float4*)&Bs[kk][tx * 4];
                unsigned long long bb[4];
                bb[0] = pack2(b4.x, b4.x); bb[1] = pack2(b4.y, b4.y);
                bb[2] = pack2(b4.z, b4.z); bb[3] = pack2(b4.w, b4.w);
                #pragma unroll
                for (int p = 0; p < 4; p++)
                    #pragma unroll
                    for (int n = 0; n < 4; n++)
                        fma2(acc[p][n], a2[p], bb[n]);
            }
        }
        #pragma unroll
        for (int p = 0; p < 4; p++) {
            int m = m0 + ty * 8 + p * 2;
            #pragma unroll
            for (int n = 0; n < 4; n++) {
                float2 f = unpack2(acc[p][n]);
                int col = n0 + tx * 4 + n;
                float bv = bh[col];
                g_enc_feat[(size_t)m * 256 + col] = f.x + bv;
                g_enc_feat[(size_t)(m + 1) * 256 + col] = f.y + bv;
            }
        }
    }
}

// ---------------- dec_feat batched GEMM: [1600,512]x[512,256] --------------
__global__ void __launch_bounds__(256)
k_dec_gemm(const float* __restrict__ bs_) {
    __shared__ float As[64][17];
    __shared__ float Bs[16][64];
    const int m0 = blockIdx.y * 64;
    const int n0 = blockIdx.x * 64;
    const int tid = threadIdx.x;
    const int tx = tid & 15, ty = tid >> 4;
    float acc[4][4] = {};
    for (int k0 = 0; k0 < 512; k0 += 16) {
        for (int i = tid; i < 64 * 16; i += 256) {
            int m = i >> 4, k = i & 15;
            int r = m0 + m;
            int t = r >> 4, bb = r & 15;
            int kk = k0 + k;
            float v = (kk < 256)
                ? g_h_all[(size_t)(t + 1) * B * H + bb * H + kk]
                : g_c_all[(size_t)(t + 1) * B * H + bb * H + kk - 256];
            As[m][k] = v;
        }
        for (int i = tid; i < 16 * 64; i += 256) {
            int k = i >> 6, n = i & 63;
            Bs[k][n] = g_WsT[(size_t)(k0 + k) * 256 + n0 + n];
        }
        __syncthreads();
        #pragma unroll
        for (int kk = 0; kk < 16; kk++) {
            float a0 = As[ty * 4 + 0][kk], a1 = As[ty * 4 + 1][kk];
            float a2 = As[ty * 4 + 2][kk], a3 = As[ty * 4 + 3][kk];
            float4 b4 = *(const float4*)&Bs[kk][tx * 4];
            acc[0][0] += a0 * b4.x; acc[0][1] += a0 * b4.y; acc[0][2] += a0 * b4.z; acc[0][3] += a0 * b4.w;
            acc[1][0] += a1 * b4.x; acc[1][1] += a1 * b4.y; acc[1][2] += a1 * b4.z; acc[1][3] += a1 * b4.w;
            acc[2][0] += a2 * b4.x; acc[2][1] += a2 * b4.y; acc[2][2] += a2 * b4.z; acc[2][3] += a2 * b4.w;
            acc[3][0] += a3 * b4.x; acc[3][1] += a3 * b4.y; acc[3][2] += a3 * b4.z; acc[3][3] += a3 * b4.w;
        }
        __syncthreads();
    }
    #pragma unroll
    for (int i = 0; i < 4; i++) {
        int r = m0 + ty * 4 + i;
        #pragma unroll
        for (int j = 0; j < 4; j++) {
            int n = n0 + tx * 4 + j;
            g_dec_all[(size_t)r * 256 + n] = acc[i][j] + bs_[n];
        }
    }
}

// ---------------- batched e-scores: warp per (b,l), loop t -----------------
// tanh via E=exp2(arg*2log2e), A=E+1; 4-way grouped reciprocal: 1.25 MUFU/tanh
__global__ void __launch_bounds__(256)
k_escore_all(const float* __restrict__ v) {
    const float L2E2 = 2.885390082f;   // 2*log2(e)
    const int tid = threadIdx.x;
    const int lane = tid & 31, wid = tid >> 5;
    const int gwarp = blockIdx.x * 8 + wid;
    const int b = gwarp >> 11;
    const int l = gwarp & 2047;

    const float4* ef4 = (const float4*)(g_enc_feat + ((size_t)(b * L + l)) * H);
    const float4* v4 = (const float4*)v;
    float4 ea = ef4[lane * 2], eb = ef4[lane * 2 + 1];
    float4 va = v4[lane * 2], vb = v4[lane * 2 + 1];
    // Vtot = sum of all v (same in all lanes after reduce)
    float Vtot = wreduce(va.x + va.y + va.z + va.w + vb.x + vb.y + vb.z + vb.w);
    // 2*v per lane
    float4 w2a = make_float4(2.f * va.x, 2.f * va.y, 2.f * va.z, 2.f * va.w);
    float4 w2b = make_float4(2.f * vb.x, 2.f * vb.y, 2.f * vb.z, 2.f * vb.w);

    float* eout = g_e_tr + ((size_t)(b * L + l)) * 128;

    #pragma unroll 1
    for (int c = 0; c < 4; c++) {
        float ereg = 0.f;
        int tmax = T_STEPS - c * 32;
        if (tmax > 32) tmax = 32;
        #pragma unroll 1
        for (int tt = 0; tt < tmax; tt++) {
            int t = c * 32 + tt;
            const float4* d4 = (const float4*)(g_dec_all + (size_t)(t * B + b) * H);
            float4 dfa = d4[lane * 2], dfb = d4[lane * 2 + 1];
            // args, clamped to ±10 (tanh saturated within fp32 beyond)
            float x0 = fminf(fmaxf(ea.x + dfa.x, -10.f), 10.f);
            float x1 = fminf(fmaxf(ea.y + dfa.y, -10.f), 10.f);
            float x2 = fminf(fmaxf(ea.z + dfa.z, -10.f), 10.f);
            float x3 = fminf(fmaxf(ea.w + dfa.w, -10.f), 10.f);
            float x4 = fminf(fmaxf(eb.x + dfb.x, -10.f), 10.f);
            float x5 = fminf(fmaxf(eb.y + dfb.y, -10.f), 10.f);
            float x6 = fminf(fmaxf(eb.z + dfb.z, -10.f), 10.f);
            float x7 = fminf(fmaxf(eb.w + dfb.w, -10.f), 10.f);
            float A0 = ex2(x0 * L2E2) + 1.f;
            float A1 = ex2(x1 * L2E2) + 1.f;
            float A2 = ex2(x2 * L2E2) + 1.f;
            float A3 = ex2(x3 * L2E2) + 1.f;
            float A4 = ex2(x4 * L2E2) + 1.f;
            float A5 = ex2(x5 * L2E2) + 1.f;
            float A6 = ex2(x6 * L2E2) + 1.f;
            float A7 = ex2(x7 * L2E2) + 1.f;
            // group 0: A0..A3
            float P01 = A0 * A1, P23 = A2 * A3;
            float r0 = rcp(P01 * P23);
            float r01 = r0 * P23, r23 = r0 * P01;
            // group 1: A4..A7
            float P45 = A4 * A5, P67 = A6 * A7;
            float r1 = rcp(P45 * P67);
            float r45 = r1 * P67, r67 = r1 * P45;
            // acc = sum 2*v_i / A_i   (tanh_i = 1 - 2/A_i)
            float acc = w2a.x * (r01 * A1);
            acc = fmaf(w2a.y, r01 * A0, acc);
            acc = fmaf(w2a.z, r23 * A3, acc);
            acc = fmaf(w2a.w, r23 * A2, acc);
            acc = fmaf(w2b.x, r45 * A5, acc);
            acc = fmaf(w2b.y, r45 * A4, acc);
            acc = fmaf(w2b.z, r67 * A7, acc);
            acc = fmaf(w2b.w, r67 * A6, acc);
            float s = Vtot - wreduce(acc);
            if (tt == lane) ereg = s;
        }
        if (c * 32 + lane < T_STEPS) eout[c * 32 + lane] = ereg;
    }
}

// ---------------- batched softmax: block per (t,b) -------------------------
__global__ void __launch_bounds__(256)
k_softmax_all(const float* __restrict__ mask, float* __restrict__ o_attn) {
    __shared__ float red[16];
    const int r = blockIdx.x;
    const int t = r >> 4, b = r & 15;
    const int tid = threadIdx.x;
    const int lane = tid & 31, wid = tid >> 5;

    const float* mrow = mask + (size_t)b * L;

    float ev[8], mv[8];
    float mx = -3.4e38f;
    #pragma unroll
    for (int i = 0; i < 8; i++) {
        int l = tid + i * 256;
        ev[i] = g_e_tr[((size_t)(b * L + l)) * 128 + t];
        mv[i] = mrow[l];
        mx = fmaxf(mx, ev[i]);
    }
    mx = wmax(mx);
    if (lane == 0) red[wid] = mx;
    __syncthreads();
    mx = red[0];
    #pragma unroll
    for (int i = 1; i < 8; i++) mx = fmaxf(mx, red[i]);

    float pv[8];
    float s = 0.f;
    #pragma unroll
    for (int i = 0; i < 8; i++) {
        pv[i] = __expf(ev[i] - mx) * mv[i];
        s += pv[i];
    }
    s = wreduce(s);
    if (lane == 0) red[8 + wid] = s;
    __syncthreads();
    s = 0.f;
    #pragma unroll
    for (int i = 0; i < 8; i++) s += red[8 + i];
    float inv = __fdividef(1.f, s);
    #pragma unroll
    for (int i = 0; i < 8; i++)
        o_attn[(size_t)r * L + tid + i * 256] = pv[i] * inv;
}

// ---------------- ctx batched GEMM per b: [128(t),2048]x[2048,512] ---------
__global__ void __launch_bounds__(256)
k_ctx_gemm(const float* __restrict__ enc, const float* __restrict__ o_attn) {
    __shared__ __align__(16) float Ast[16][132];
    __shared__ __align__(16) float Bs[16][64];
    const int tid = threadIdx.x;
    const int b = blockIdx.y;
    const int n0 = blockIdx.x * 64;
    const int tx = tid & 15, ty = tid >> 4;
    unsigned long long acc[4][4];
    #pragma unroll
    for (int p = 0; p < 4; p++)
        #pragma unroll
        for (int n = 0; n < 4; n++) acc[p][n] = 0ull;

    for (int k0 = 0; k0 < L; k0 += 16) {
        __syncthreads();
        #pragma unroll
        for (int u = 0; u < 2; u++) {
            int idx = u * 256 + tid;
            int row = idx >> 2, q = idx & 3;
            float4 f = make_float4(0.f, 0.f, 0.f, 0.f);
            if (row < T_STEPS)
                f = *(const float4*)(o_attn + ((size_t)(row * B + b)) * L + k0 + q * 4);
            Ast[q * 4 + 0][row] = f.x;
            Ast[q * 4 + 1][row] = f.y;
            Ast[q * 4 + 2][row] = f.z;
            Ast[q * 4 + 3][row] = f.w;
        }
        {
            int kk = tid >> 4, n4 = (tid & 15) * 4;
            *(float4*)&Bs[kk][n4] =
                *(const float4*)(enc + ((size_t)(b * L + k0 + kk)) * (2 * H) + n0 + n4);
        }
        __syncthreads();
        #pragma unroll
        for (int kk = 0; kk < 16; kk++) {
            unsigned long long a2[4];
            #pragma unroll
            for (int p = 0; p < 4; p++)
                a2[p] = *(const unsigned long long*)&Ast[kk][ty * 8 + p * 2];
            float4 b4 = *(const float4*)&Bs[kk][tx * 4];
            unsigned long long bb[4];
            bb[0] = pack2(b4.x, b4.x); bb[1] = pack2(b4.y, b4.y);
            bb[2] = pack2(b4.z, b4.z); bb[3] = pack2(b4.w, b4.w);
            #pragma unroll
            for (int p = 0; p < 4; p++)
                #pragma unroll
                for (int n = 0; n < 4; n++)
                    fma2(acc[p][n], a2[p], bb[n]);
        }
    }
    #pragma unroll
    for (int p = 0; p < 4; p++) {
        int t = ty * 8 + p * 2;
        #pragma unroll
        for (int n = 0; n < 4; n++) {
            float2 f = unpack2(acc[p][n]);
            int col = n0 + tx * 4 + n;
            if (t < T_STEPS)
                g_ctx_all[(size_t)(t * B + b) * (2 * H) + col] = f.x;
            if (t + 1 < T_STEPS)
                g_ctx_all[(size_t)((t + 1) * B + b) * (2 * H) + col] = f.y;
        }
    }
}

// ---------------- out batched GEMM: [1600,768]x[768,256] -------------------
__global__ void __launch_bounds__(256)
k_out_gemm(const float* __restrict__ bout, float* __restrict__ o_out) {
    __shared__ float As[64][17];
    __shared__ float Bs[16][64];
    const int m0 = blockIdx.y * 64;
    const int n0 = blockIdx.x * 64;
    const int tid = threadIdx.x;
    const int tx = tid & 15, ty = tid >> 4;
    float acc[4][4] = {};
    for (int k0 = 0; k0 < 768; k0 += 16) {
        for (int i = tid; i < 64 * 16; i += 256) {
            int m = i >> 4, k = i & 15;
            int r = m0 + m;
            int t = r >> 4, bb = r & 15;
            int kk = k0 + k;
            float v = (kk < 256)
                ? g_h_all[(size_t)(t + 1) * B * H + bb * H + kk]
                : g_ctx_all[(size_t)r * 512 + kk - 256];
            As[m][k] = v;
        }
        for (int i = tid; i < 16 * 64; i += 256) {
            int k = i >> 6, n = i & 63;
            Bs[k][n] = g_WoutT[(size_t)(k0 + k) * 256 + n0 + n];
        }
        __syncthreads();
        #pragma unroll
        for (int kk = 0; kk < 16; kk++) {
            float a0 = As[ty * 4 + 0][kk], a1 = As[ty * 4 + 1][kk];
            float a2 = As[ty * 4 + 2][kk], a3 = As[ty * 4 + 3][kk];
            float4 b4 = *(const float4*)&Bs[kk][tx * 4];
            acc[0][0] += a0 * b4.x; acc[0][1] += a0 * b4.y; acc[0][2] += a0 * b4.z; acc[0][3] += a0 * b4.w;
            acc[1][0] += a1 * b4.x; acc[1][1] += a1 * b4.y; acc[1][2] += a1 * b4.z; acc[1][3] += a1 * b4.w;
            acc[2][0] += a2 * b4.x; acc[2][1] += a2 * b4.y; acc[2][2] += a2 * b4.z; acc[2][3] += a2 * b4.w;
            acc[3][0] += a3 * b4.x; acc[3][1] += a3 * b4.y; acc[3][2] += a3 * b4.z; acc[3][3] += a3 * b4.w;
        }
        __syncthreads();
    }
    #pragma unroll
    for (int i = 0; i < 4; i++) {
        int r = m0 + ty * 4 + i;
        #pragma unroll
        for (int j = 0; j < 4; j++) {
            int n = n0 + tx * 4 + j;
            o_out[(size_t)r * 256 + n] = acc[i][j] + bout[n];
        }
    }
}

// ---------------- p_gen batched + h_f/c_f ----------------------------------
__global__ void __launch_bounds__(256)
k_pgen(const float* __restrict__ Wpg, const float* __restrict__ bpg,
       float* __restrict__ o_pgen, float* __restrict__ o_hf, float* __restrict__ o_cf) {
    const int tid = threadIdx.x;
    const int lane = tid & 31, wid = tid >> 5;
    const int blk = blockIdx.x;

    if (blk < 200) {
        const int r = blk * 8 + wid;
        const int t = r >> 4, bb = r & 15;
        float s = 0.f;
        for (int k = lane; k < 4 * H + E; k += 32) {
            float cv;
            if (k < 2 * H) cv = g_ctx_all[(size_t)r * 512 + k];
            else if (k < 3 * H) cv = g_h_all[(size_t)(t + 1) * B * H + bb * H + k - 2 * H];
            else if (k < 4 * H) cv = g_c_all[(size_t)(t + 1) * B * H + bb * H + k - 3 * H];
            else cv = g_x_all[(size_t)r * E + k - 4 * H];
            s += cv * Wpg[k];
        }
        s = wreduce(s);
        if (lane == 0) o_pgen[r] = sig_f(s + bpg[0]);
    } else {
        for (int i = (blk - 200) * 256 + tid; i < B * H; i += 512) {
            o_hf[i] = g_h_all[(size_t)T_STEPS * B * H + i];
            o_cf[i] = g_c_all[(size_t)T_STEPS * B * H + i];
        }
    }
}

// ---------------- host launcher ----------------
extern "C" void kernel_launch(void* const* d_in, const int* in_sizes, int n_in,
                              void* d_out, int out_size) {
    const float* dec_in = (const float*)d_in[0];
    const float* h0     = (const float*)d_in[1];
    const float* c0     = (const float*)d_in[2];
    const float* enc    = (const float*)d_in[3];
    const float* mask   = (const float*)d_in[4];
    const float* Wh     = (const float*)d_in[5];
    const float* bh     = (const float*)d_in[6];
    const float* Ws_    = (const float*)d_in[7];
    const float* bs_    = (const float*)d_in[8];
    const float* v      = (const float*)d_in[9];
    const float* Wx     = (const float*)d_in[10];
    const float* bx     = (const float*)d_in[11];
    const float* Wih    = (const float*)d_in[12];
    const float* bih    = (const float*)d_in[13];
    const float* Whh    = (const float*)d_in[14];
    const float* bhh    = (const float*)d_in[15];
    const float* Wpg    = (const float*)d_in[16];
    const float* bpg    = (const float*)d_in[17];
    const float* Wout   = (const float*)d_in[18];
    const float* bout   = (const float*)d_in[19];

    float* out = (float*)d_out;
    float* o_outputs = out;                                  // [T,B,H]
    float* o_hf = o_outputs + (size_t)T_STEPS * B * H;       // [B,H]
    float* o_cf = o_hf + B * H;                              // [B,H]
    float* o_attn = o_cf + B * H;                            // [T,B,L]
    float* o_pgen = o_attn + (size_t)T_STEPS * B * L;        // [T,B,1]

    k_prep<<<2384, 256>>>(Wh, Ws_, Wout, Wih, Wx, h0, c0);
    k_xg<<<dim3(2, 25), 256>>>(dec_in, bx);
    k_gig<<<dim3(16, 25), 256>>>(bih, bhh);

    k_fat<<<CHAIN_BLOCKS + 1024, 256>>>(Whh, enc, bh);

    k_dec_gemm<<<dim3(4, 25), 256>>>(bs_);
    k_escore_all<<<4096, 256>>>(v);
    k_softmax_all<<<1600, 256>>>(mask, o_attn);
    k_ctx_gemm<<<dim3(8, 16), 256>>>(enc, o_attn);
    k_out_gemm<<<dim3(4, 25), 256>>>(bout, o_outputs);
    k_pgen<<<202, 256>>>(Wpg, bpg, o_pgen, o_hf, o_cf);
}

// round 11
// speedup vs baseline: 1.4787x; 1.4787x over previous
#include <cuda_runtime.h>
#include <cstdint>

#define T_STEPS 100
#define B 16
#define E 128
#define H 256
#define L 2048
#define CHAIN_BLOCKS 64

// ---------------- device scratch (static allocations only) ----------------
__device__ float g_enc_feat[B * L * H];                 // 33.5 MB — holds E=exp(2(ef+bh))
__device__ float g_WhT[512 * 256];
__device__ float g_WsT[512 * 256];
__device__ float g_WoutT[768 * 256];
__device__ float g_WihT[128 * 1024];
__device__ float g_WxT[128 * 128];
__device__ float g_x_all[T_STEPS * B * E];
__device__ float g_gi[T_STEPS * B * 4 * H];
__device__ float g_h_all[(T_STEPS + 1) * B * H];
__device__ float g_c_all[(T_STEPS + 1) * B * H];
__device__ float g_dec_all[T_STEPS * B * H];            // holds D=exp(2*dec)
__device__ float g_ctx_all[T_STEPS * B * 2 * H];
__device__ float g_e_tr[B * L * 128];                   // [b][l][t(pad128)]
__device__ unsigned g_barc;

#define L2E2 2.885390082f   // 2*log2(e)

// ---------------- fast math helpers ----------------
__device__ __forceinline__ float tanh_f(float x) {
    float e = __expf(2.f * x);
    return 1.f - __fdividef(2.f, e + 1.f);
}
__device__ __forceinline__ float sig_f(float x) {
    return __fdividef(1.f, 1.f + __expf(-x));
}
__device__ __forceinline__ float ex2(float x) {
    float r;
    asm("ex2.approx.ftz.f32 %0, %1;" : "=f"(r) : "f"(x));
    return r;
}
__device__ __forceinline__ float rcp(float x) {
    float r;
    asm("rcp.approx.ftz.f32 %0, %1;" : "=f"(r) : "f"(x));
    return r;
}
__device__ __forceinline__ float wreduce(float s) {
    #pragma unroll
    for (int off = 16; off; off >>= 1) s += __shfl_xor_sync(0xffffffffu, s, off);
    return s;
}
__device__ __forceinline__ float wmax(float s) {
    #pragma unroll
    for (int off = 16; off; off >>= 1) s = fmaxf(s, __shfl_xor_sync(0xffffffffu, s, off));
    return s;
}
__device__ __forceinline__ unsigned long long pack2(float x, float y) {
    unsigned long long r;
    asm("mov.b64 %0, {%1, %2};" : "=l"(r) : "f"(x), "f"(y));
    return r;
}
__device__ __forceinline__ void fma2(unsigned long long& d, unsigned long long a, unsigned long long b) {
    asm("fma.rn.f32x2 %0, %1, %2, %3;" : "=l"(d) : "l"(a), "l"(b), "l"(d));
}
__device__ __forceinline__ float2 unpack2(unsigned long long v) {
    float2 f;
    asm("mov.b64 {%0, %1}, %2;" : "=f"(f.x), "=f"(f.y) : "l"(v));
    return f;
}

// ---------------- prep: all transposes + h/c init + barrier reset ----------
__global__ void k_prep(const float* __restrict__ Wh, const float* __restrict__ Ws_,
                       const float* __restrict__ Wout, const float* __restrict__ Wih,
                       const float* __restrict__ Wx,
                       const float* __restrict__ h0, const float* __restrict__ c0) {
    int blk = blockIdx.x, tid = threadIdx.x;
    if (blk == 0 && tid == 0) g_barc = 0u;
    if (blk < 512) {
        int i = blk * 256 + tid;
        int j = i & 255, k = i >> 8;
        g_WhT[i] = Wh[j * 512 + k];
    } else if (blk < 1024) {
        int i = (blk - 512) * 256 + tid;
        int j = i & 255, k = i >> 8;
        g_WsT[i] = Ws_[j * 512 + k];
    } else if (blk < 1792) {
        int i = (blk - 1024) * 256 + tid;
        int j = i & 255, k = i >> 8;
        g_WoutT[i] = Wout[j * 768 + k];
    } else if (blk < 2304) {
        int i = (blk - 1792) * 256 + tid;
        int j = i & 1023, k = i >> 10;
        g_WihT[i] = Wih[j * 128 + k];
    } else if (blk < 2368) {
        int i = (blk - 2304) * 256 + tid;
        int j = i & 127, k = i >> 7;
        g_WxT[i] = Wx[j * (2 * H + E) + k];
    } else {
        int i = (blk - 2368) * 256 + tid;
        g_h_all[i] = h0[i];
        g_c_all[i] = c0[i];
    }
}

// ---------------- x GEMM: [1600,128] = dec_in @ WxT + bx -------------------
__global__ void __launch_bounds__(256)
k_xg(const float* __restrict__ Din, const float* __restrict__ bx) {
    __shared__ float As[64][17];
    __shared__ float Bs[16][64];
    const int m0 = blockIdx.y * 64;
    const int n0 = blockIdx.x * 64;
    const int tid = threadIdx.x;
    const int tx = tid & 15, ty = tid >> 4;
    float acc[4][4] = {};
    for (int k0 = 0; k0 < 128; k0 += 16) {
        for (int i = tid; i < 64 * 16; i += 256) {
            int m = i >> 4, k = i & 15;
            As[m][k] = Din[(size_t)(m0 + m) * 128 + k0 + k];
        }
        for (int i = tid; i < 16 * 64; i += 256) {
            int k = i >> 6, n = i & 63;
            Bs[k][n] = g_WxT[(size_t)(k0 + k) * 128 + n0 + n];
        }
        __syncthreads();
        #pragma unroll
        for (int kk = 0; kk < 16; kk++) {
            float a0 = As[ty * 4 + 0][kk], a1 = As[ty * 4 + 1][kk];
            float a2 = As[ty * 4 + 2][kk], a3 = As[ty * 4 + 3][kk];
            float4 b4 = *(const float4*)&Bs[kk][tx * 4];
            acc[0][0] += a0 * b4.x; acc[0][1] += a0 * b4.y; acc[0][2] += a0 * b4.z; acc[0][3] += a0 * b4.w;
            acc[1][0] += a1 * b4.x; acc[1][1] += a1 * b4.y; acc[1][2] += a1 * b4.z; acc[1][3] += a1 * b4.w;
            acc[2][0] += a2 * b4.x; acc[2][1] += a2 * b4.y; acc[2][2] += a2 * b4.z; acc[2][3] += a2 * b4.w;
            acc[3][0] += a3 * b4.x; acc[3][1] += a3 * b4.y; acc[3][2] += a3 * b4.z; acc[3][3] += a3 * b4.w;
        }
        __syncthreads();
    }
    #pragma unroll
    for (int i = 0; i < 4; i++) {
        int r = m0 + ty * 4 + i;
        #pragma unroll
        for (int j = 0; j < 4; j++) {
            int n = n0 + tx * 4 + j;
            g_x_all[(size_t)r * 128 + n] = acc[i][j] + bx[n];
        }
    }
}

// ---------------- gi GEMM: [1600,1024] = x_all @ WihT + bih + bhh ----------
__global__ void __launch_bounds__(256)
k_gig(const float* __restrict__ bih, const float* __restrict__ bhh) {
    __shared__ float As[64][17];
    __shared__ float Bs[16][64];
    const int m0 = blockIdx.y * 64;
    const int n0 = blockIdx.x * 64;
    const int tid = threadIdx.x;
    const int tx = tid & 15, ty = tid >> 4;
    float acc[4][4] = {};
    for (int k0 = 0; k0 < 128; k0 += 16) {
        for (int i = tid; i < 64 * 16; i += 256) {
            int m = i >> 4, k = i & 15;
            As[m][k] = g_x_all[(size_t)(m0 + m) * 128 + k0 + k];
        }
        for (int i = tid; i < 16 * 64; i += 256) {
            int k = i >> 6, n = i & 63;
            Bs[k][n] = g_WihT[(size_t)(k0 + k) * 1024 + n0 + n];
        }
        __syncthreads();
        #pragma unroll
        for (int kk = 0; kk < 16; kk++) {
            float a0 = As[ty * 4 + 0][kk], a1 = As[ty * 4 + 1][kk];
            float a2 = As[ty * 4 + 2][kk], a3 = As[ty * 4 + 3][kk];
            float4 b4 = *(const float4*)&Bs[kk][tx * 4];
            acc[0][0] += a0 * b4.x; acc[0][1] += a0 * b4.y; acc[0][2] += a0 * b4.z; acc[0][3] += a0 * b4.w;
            acc[1][0] += a1 * b4.x; acc[1][1] += a1 * b4.y; acc[1][2] += a1 * b4.z; acc[1][3] += a1 * b4.w;
            acc[2][0] += a2 * b4.x; acc[2][1] += a2 * b4.y; acc[2][2] += a2 * b4.z; acc[2][3] += a2 * b4.w;
            acc[3][0] += a3 * b4.x; acc[3][1] += a3 * b4.y; acc[3][2] += a3 * b4.z; acc[3][3] += a3 * b4.w;
        }
        __syncthreads();
    }
    #pragma unroll
    for (int i = 0; i < 4; i++) {
        int r = m0 + ty * 4 + i;
        #pragma unroll
        for (int j = 0; j < 4; j++) {
            int n = n0 + tx * 4 + j;
            g_gi[(size_t)r * 1024 + n] = acc[i][j] + bih[n] + bhh[n];
        }
    }
}

// ================= FAT kernel: chain (blocks 0..63) ∥ encfeat (64..1087) ===
__global__ void __launch_bounds__(256)
k_fat(const float* __restrict__ Whh, const float* __restrict__ ES,
      const float* __restrict__ bh) {
    __shared__ __align__(16) float smem_u[4096];   // 16 KB union
    const int tid = threadIdx.x;

    if (blockIdx.x < CHAIN_BLOCKS) {
        // ---------------- persistent LSTM chain ----------------
        float* sh = smem_u;
        const int lane = tid & 31, wid = tid >> 5;
        const int gw = blockIdx.x * 8 + wid;
        const int j = gw >> 1;
        const int half = gw & 1;

        float w[4][8];
        #pragma unroll
        for (int g = 0; g < 4; g++)
            #pragma unroll
            for (int i = 0; i < 8; i++)
                w[g][i] = Whh[(size_t)(g * H + j) * H + lane + i * 32];

        float creg = 0.f;
        if (lane < 8) creg = g_c_all[(half * 8 + lane) * H + j];

        for (int t = 0; t < T_STEPS; t++) {
            {
                const float4* hsrc4 = (const float4*)(g_h_all + (size_t)t * B * H);
                float4* sh4 = (float4*)sh;
                #pragma unroll
                for (int i = 0; i < 4; i++) sh4[tid + i * 256] = __ldcg(hsrc4 + tid + i * 256);
            }
            __syncthreads();

            float gi0 = 0.f, gi1 = 0.f, gi2 = 0.f, gi3 = 0.f;
            if (lane < 8) {
                const float* gi = g_gi + (size_t)(t * B + half * 8 + lane) * 4 * H;
                gi0 = gi[j]; gi1 = gi[H + j]; gi2 = gi[2 * H + j]; gi3 = gi[3 * H + j];
            }

            float acc[4];
            #pragma unroll 2
            for (int i8 = 0; i8 < 8; i8++) {
                const float* hb = sh + (half * 8 + i8) * H;
                #pragma unroll
                for (int g = 0; g < 4; g++) {
                    float s = 0.f;
                    #pragma unroll
                    for (int i = 0; i < 8; i++) s += w[g][i] * hb[lane + i * 32];
                    acc[g] = wreduce(s);
                }
                if (lane == i8) {
                    float ig = acc[0] + gi0;
                    float fg = acc[1] + gi1;
                    float gg = acc[2] + gi2;
                    float og = acc[3] + gi3;
                    float cn = sig_f(fg) * creg + sig_f(ig) * tanh_f(gg);
                    float hn = sig_f(og) * tanh_f(cn);
                    creg = cn;
                    int bb = half * 8 + i8;
                    g_c_all[(size_t)(t + 1) * B * H + bb * H + j] = cn;
                    g_h_all[(size_t)(t + 1) * B * H + bb * H + j] = hn;
                }
            }

            __syncthreads();
            if (tid == 0) {
                __threadfence();
                atomicAdd(&g_barc, 1u);
                unsigned target = (unsigned)CHAIN_BLOCKS * (unsigned)(t + 1);
                while (*(volatile unsigned*)&g_barc < target) __nanosleep(32);
                __threadfence();
            }
            __syncthreads();
        }
    } else {
        // ---------------- enc_feat GEMM tile → stores E = exp(2(ef+bh)) ----
        float (*Ast)[132] = (float(*)[132])smem_u;
        float (*Bs)[64] = (float(*)[64])(smem_u + 2112);
        const int eb = blockIdx.x - CHAIN_BLOCKS;
        const int m0 = (eb >> 2) * 128;
        const int n0 = (eb & 3) * 64;
        const int tx = tid & 15, ty = tid >> 4;
        unsigned long long acc[4][4];
        #pragma unroll
        for (int p = 0; p < 4; p++)
            #pragma unroll
            for (int n = 0; n < 4; n++) acc[p][n] = 0ull;

        for (int k0 = 0; k0 < 512; k0 += 16) {
            __syncthreads();
            #pragma unroll
            for (int u = 0; u < 2; u++) {
                int idx = u * 256 + tid;
                int row = idx >> 2, q = idx & 3;
                float4 f = *(const float4*)(ES + (size_t)(m0 + row) * 512 + k0 + q * 4);
                Ast[q * 4 + 0][row] = f.x;
                Ast[q * 4 + 1][row] = f.y;
                Ast[q * 4 + 2][row] = f.z;
                Ast[q * 4 + 3][row] = f.w;
            }
            {
                int kk = tid >> 4, n4 = (tid & 15) * 4;
                *(float4*)&Bs[kk][n4] = *(const float4*)(g_WhT + (size_t)(k0 + kk) * 256 + n0 + n4);
            }
            __syncthreads();
            #pragma unroll
            for (int kk = 0; kk < 16; kk++) {
                unsigned long long a2[4];
                #pragma unroll
                for (int p = 0; p < 4; p++)
                    a2[p] = *(const unsigned long long*)&Ast[kk][ty * 8 + p * 2];
                float4 b4 = *(const float4*)&Bs[kk][tx * 4];
                unsigned long long bb[4];
                bb[0] = pack2(b4.x, b4.x); bb[1] = pack2(b4.y, b4.y);
                bb[2] = pack2(b4.z, b4.z); bb[3] = pack2(b4.w, b4.w);
                #pragma unroll
                for (int p = 0; p < 4; p++)
                    #pragma unroll
                    for (int n = 0; n < 4; n++)
                        fma2(acc[p][n], a2[p], bb[n]);
            }
        }
        #pragma unroll
        for (int p = 0; p < 4; p++) {
            int m = m0 + ty * 8 + p * 2;
            #pragma unroll
            for (int n = 0; n < 4; n++) {
                float2 f = unpack2(acc[p][n]);
                int col = n0 + tx * 4 + n;
                float bv = bh[col];
                g_enc_feat[(size_t)m * 256 + col] = ex2((f.x + bv) * L2E2);
                g_enc_feat[(size_t)(m + 1) * 256 + col] = ex2((f.y + bv) * L2E2);
            }
        }
    }
}

// ---------------- dec_feat batched GEMM → stores D = exp(2*dec) ------------
__global__ void __launch_bounds__(256)
k_dec_gemm(const float* __restrict__ bs_) {
    __shared__ float As[64][17];
    __shared__ float Bs[16][64];
    const int m0 = blockIdx.y * 64;
    const int n0 = blockIdx.x * 64;
    const int tid = threadIdx.x;
    const int tx = tid & 15, ty = tid >> 4;
    float acc[4][4] = {};
    for (int k0 = 0; k0 < 512; k0 += 16) {
        for (int i = tid; i < 64 * 16; i += 256) {
            int m = i >> 4, k = i & 15;
            int r = m0 + m;
            int t = r >> 4, bb = r & 15;
            int kk = k0 + k;
            float v = (kk < 256)
                ? g_h_all[(size_t)(t + 1) * B * H + bb * H + kk]
                : g_c_all[(size_t)(t + 1) * B * H + bb * H + kk - 256];
            As[m][k] = v;
        }
        for (int i = tid; i < 16 * 64; i += 256) {
            int k = i >> 6, n = i & 63;
            Bs[k][n] = g_WsT[(size_t)(k0 + k) * 256 + n0 + n];
        }
        __syncthreads();
        #pragma unroll
        for (int kk = 0; kk < 16; kk++) {
            float a0 = As[ty * 4 + 0][kk], a1 = As[ty * 4 + 1][kk];
            float a2 = As[ty * 4 + 2][kk], a3 = As[ty * 4 + 3][kk];
            float4 b4 = *(const float4*)&Bs[kk][tx * 4];
            acc[0][0] += a0 * b4.x; acc[0][1] += a0 * b4.y; acc[0][2] += a0 * b4.z; acc[0][3] += a0 * b4.w;
            acc[1][0] += a1 * b4.x; acc[1][1] += a1 * b4.y; acc[1][2] += a1 * b4.z; acc[1][3] += a1 * b4.w;
            acc[2][0] += a2 * b4.x; acc[2][1] += a2 * b4.y; acc[2][2] += a2 * b4.z; acc[2][3] += a2 * b4.w;
            acc[3][0] += a3 * b4.x; acc[3][1] += a3 * b4.y; acc[3][2] += a3 * b4.z; acc[3][3] += a3 * b4.w;
        }
        __syncthreads();
    }
    #pragma unroll
    for (int i = 0; i < 4; i++) {
        int r = m0 + ty * 4 + i;
        #pragma unroll
        for (int j = 0; j < 4; j++) {
            int n = n0 + tx * 4 + j;
            g_dec_all[(size_t)r * 256 + n] = ex2((acc[i][j] + bs_[n]) * L2E2);
        }
    }
}

// ---------------- batched e-scores: warp per (b,l), loop t -----------------
// e = Vtot - sum_i 2*v_i / (E_i * D_i + 1),  E=exp(2ef) resident, D=exp(2dec)
__global__ void __launch_bounds__(256)
k_escore_all(const float* __restrict__ v) {
    const int tid = threadIdx.x;
    const int lane = tid & 31, wid = tid >> 5;
    const int gwarp = blockIdx.x * 8 + wid;
    const int b = gwarp >> 11;
    const int l = gwarp & 2047;

    const float4* ef4 = (const float4*)(g_enc_feat + ((size_t)(b * L + l)) * H);
    const float4* v4 = (const float4*)v;
    float4 Ea = ef4[lane * 2], Eb = ef4[lane * 2 + 1];
    float4 va = v4[lane * 2], vb = v4[lane * 2 + 1];
    float Vtot = wreduce(va.x + va.y + va.z + va.w + vb.x + vb.y + vb.z + vb.w);
    float4 w2a = make_float4(2.f * va.x, 2.f * va.y, 2.f * va.z, 2.f * va.w);
    float4 w2b = make_float4(2.f * vb.x, 2.f * vb.y, 2.f * vb.z, 2.f * vb.w);

    float* eout = g_e_tr + ((size_t)(b * L + l)) * 128;

    #pragma unroll 1
    for (int c = 0; c < 4; c++) {
        float ereg = 0.f;
        int tmax = T_STEPS - c * 32;
        if (tmax > 32) tmax = 32;
        #pragma unroll 1
        for (int tt = 0; tt < tmax; tt++) {
            int t = c * 32 + tt;
            const float4* d4 = (const float4*)(g_dec_all + (size_t)(t * B + b) * H);
            float4 Da = d4[lane * 2], Db = d4[lane * 2 + 1];
            float A0 = fmaf(Ea.x, Da.x, 1.f);
            float A1 = fmaf(Ea.y, Da.y, 1.f);
            float A2 = fmaf(Ea.z, Da.z, 1.f);
            float A3 = fmaf(Ea.w, Da.w, 1.f);
            float A4 = fmaf(Eb.x, Db.x, 1.f);
            float A5 = fmaf(Eb.y, Db.y, 1.f);
            float A6 = fmaf(Eb.z, Db.z, 1.f);
            float A7 = fmaf(Eb.w, Db.w, 1.f);
            float acc = w2a.x * rcp(A0);
            acc = fmaf(w2a.y, rcp(A1), acc);
            acc = fmaf(w2a.z, rcp(A2), acc);
            acc = fmaf(w2a.w, rcp(A3), acc);
            acc = fmaf(w2b.x, rcp(A4), acc);
            acc = fmaf(w2b.y, rcp(A5), acc);
            acc = fmaf(w2b.z, rcp(A6), acc);
            acc = fmaf(w2b.w, rcp(A7), acc);
            float s = Vtot - wreduce(acc);
            if (tt == lane) ereg = s;
        }
        if (c * 32 + lane < T_STEPS) eout[c * 32 + lane] = ereg;
    }
}

// ---------------- batched softmax: block per (t,b) -------------------------
__global__ void __launch_bounds__(256)
k_softmax_all(const float* __restrict__ mask, float* __restrict__ o_attn) {
    __shared__ float red[16];
    const int r = blockIdx.x;
    const int t = r >> 4, b = r & 15;
    const int tid = threadIdx.x;
    const int lane = tid & 31, wid = tid >> 5;

    const float* mrow = mask + (size_t)b * L;

    float ev[8], mv[8];
    float mx = -3.4e38f;
    #pragma unroll
    for (int i = 0; i < 8; i++) {
        int l = tid + i * 256;
        ev[i] = g_e_tr[((size_t)(b * L + l)) * 128 + t];
        mv[i] = mrow[l];
        mx = fmaxf(mx, ev[i]);
    }
    mx = wmax(mx);
    if (lane == 0) red[wid] = mx;
    __syncthreads();
    mx = red[0];
    #pragma unroll
    for (int i = 1; i < 8; i++) mx = fmaxf(mx, red[i]);

    float pv[8];
    float s = 0.f;
    #pragma unroll
    for (int i = 0; i < 8; i++) {
        pv[i] = __expf(ev[i] - mx) * mv[i];
        s += pv[i];
    }
    s = wreduce(s);
    if (lane == 0) red[8 + wid] = s;
    __syncthreads();
    s = 0.f;
    #pragma unroll
    for (int i = 0; i < 8; i++) s += red[8 + i];
    float inv = __fdividef(1.f, s);
    #pragma unroll
    for (int i = 0; i < 8; i++)
        o_attn[(size_t)r * L + tid + i * 256] = pv[i] * inv;
}

// ---------------- ctx batched GEMM per b: [128(t),2048]x[2048,512] ---------
__global__ void __launch_bounds__(256)
k_ctx_gemm(const float* __restrict__ enc, const float* __restrict__ o_attn) {
    __shared__ __align__(16) float Ast[16][132];
    __shared__ __align__(16) float Bs[16][64];
    const int tid = threadIdx.x;
    const int b = blockIdx.y;
    const int n0 = blockIdx.x * 64;
    const int tx = tid & 15, ty = tid >> 4;
    unsigned long long acc[4][4];
    #pragma unroll
    for (int p = 0; p < 4; p++)
        #pragma unroll
        for (int n = 0; n < 4; n++) acc[p][n] = 0ull;

    for (int k0 = 0; k0 < L; k0 += 16) {
        __syncthreads();
        #pragma unroll
        for (int u = 0; u < 2; u++) {
            int idx = u * 256 + tid;
            int row = idx >> 2, q = idx & 3;
            float4 f = make_float4(0.f, 0.f, 0.f, 0.f);
            if (row < T_STEPS)
                f = *(const float4*)(o_attn + ((size_t)(row * B + b)) * L + k0 + q * 4);
            Ast[q * 4 + 0][row] = f.x;
            Ast[q * 4 + 1][row] = f.y;
            Ast[q * 4 + 2][row] = f.z;
            Ast[q * 4 + 3][row] = f.w;
        }
        {
            int kk = tid >> 4, n4 = (tid & 15) * 4;
            *(float4*)&Bs[kk][n4] =
                *(const float4*)(enc + ((size_t)(b * L + k0 + kk)) * (2 * H) + n0 + n4);
        }
        __syncthreads();
        #pragma unroll
        for (int kk = 0; kk < 16; kk++) {
            unsigned long long a2[4];
            #pragma unroll
            for (int p = 0; p < 4; p++)
                a2[p] = *(const unsigned long long*)&Ast[kk][ty * 8 + p * 2];
            float4 b4 = *(const float4*)&Bs[kk][tx * 4];
            unsigned long long bb[4];
            bb[0] = pack2(b4.x, b4.x); bb[1] = pack2(b4.y, b4.y);
            bb[2] = pack2(b4.z, b4.z); bb[3] = pack2(b4.w, b4.w);
            #pragma unroll
            for (int p = 0; p < 4; p++)
                #pragma unroll
                for (int n = 0; n < 4; n++)
                    fma2(acc[p][n], a2[p], bb[n]);
        }
    }
    #pragma unroll
    for (int p = 0; p < 4; p++) {
        int t = ty * 8 + p * 2;
        #pragma unroll
        for (int n = 0; n < 4; n++) {
            float2 f = unpack2(acc[p][n]);
            int col = n0 + tx * 4 + n;
            if (t < T_STEPS)
                g_ctx_all[(size_t)(t * B + b) * (2 * H) + col] = f.x;
            if (t + 1 < T_STEPS)
                g_ctx_all[(size_t)((t + 1) * B + b) * (2 * H) + col] = f.y;
        }
    }
}

// ---------------- out batched GEMM: [1600,768]x[768,256] -------------------
__global__ void __launch_bounds__(256)
k_out_gemm(const float* __restrict__ bout, float* __restrict__ o_out) {
    __shared__ float As[64][17];
    __shared__ float Bs[16][64];
    const int m0 = blockIdx.y * 64;
    const int n0 = blockIdx.x * 64;
    const int tid = threadIdx.x;
    const int tx = tid & 15, ty = tid >> 4;
    float acc[4][4] = {};
    for (int k0 = 0; k0 < 768; k0 += 16) {
        for (int i = tid; i < 64 * 16; i += 256) {
            int m = i >> 4, k = i & 15;
            int r = m0 + m;
            int t = r >> 4, bb = r & 15;
            int kk = k0 + k;
            float v = (kk < 256)
                ? g_h_all[(size_t)(t + 1) * B * H + bb * H + kk]
                : g_ctx_all[(size_t)r * 512 + kk - 256];
            As[m][k] = v;
        }
        for (int i = tid; i < 16 * 64; i += 256) {
            int k = i >> 6, n = i & 63;
            Bs[k][n] = g_WoutT[(size_t)(k0 + k) * 256 + n0 + n];
        }
        __syncthreads();
        #pragma unroll
        for (int kk = 0; kk < 16; kk++) {
            float a0 = As[ty * 4 + 0][kk], a1 = As[ty * 4 + 1][kk];
            float a2 = As[ty * 4 + 2][kk], a3 = As[ty * 4 + 3][kk];
            float4 b4 = *(const float4*)&Bs[kk][tx * 4];
            acc[0][0] += a0 * b4.x; acc[0][1] += a0 * b4.y; acc[0][2] += a0 * b4.z; acc[0][3] += a0 * b4.w;
            acc[1][0] += a1 * b4.x; acc[1][1] += a1 * b4.y; acc[1][2] += a1 * b4.z; acc[1][3] += a1 * b4.w;
            acc[2][0] += a2 * b4.x; acc[2][1] += a2 * b4.y; acc[2][2] += a2 * b4.z; acc[2][3] += a2 * b4.w;
            acc[3][0] += a3 * b4.x; acc[3][1] += a3 * b4.y; acc[3][2] += a3 * b4.z; acc[3][3] += a3 * b4.w;
        }
        __syncthreads();
    }
    #pragma unroll
    for (int i = 0; i < 4; i++) {
        int r = m0 + ty * 4 + i;
        #pragma unroll
        for (int j = 0; j < 4; j++) {
            int n = n0 + tx * 4 + j;
            o_out[(size_t)r * 256 + n] = acc[i][j] + bout[n];
        }
    }
}

// ---------------- p_gen batched + h_f/c_f ----------------------------------
__global__ void __launch_bounds__(256)
k_pgen(const float* __restrict__ Wpg, const float* __restrict__ bpg,
       float* __restrict__ o_pgen, float* __restrict__ o_hf, float* __restrict__ o_cf) {
    const int tid = threadIdx.x;
    const int lane = tid & 31, wid = tid >> 5;
    const int blk = blockIdx.x;

    if (blk < 200) {
        const int r = blk * 8 + wid;
        const int t = r >> 4, bb = r & 15;
        float s = 0.f;
        for (int k = lane; k < 4 * H + E; k += 32) {
            float cv;
            if (k < 2 * H) cv = g_ctx_all[(size_t)r * 512 + k];
            else if (k < 3 * H) cv = g_h_all[(size_t)(t + 1) * B * H + bb * H + k - 2 * H];
            else if (k < 4 * H) cv = g_c_all[(size_t)(t + 1) * B * H + bb * H + k - 3 * H];
            else cv = g_x_all[(size_t)r * E + k - 4 * H];
            s += cv * Wpg[k];
        }
        s = wreduce(s);
        if (lane == 0) o_pgen[r] = sig_f(s + bpg[0]);
    } else {
        for (int i = (blk - 200) * 256 + tid; i < B * H; i += 512) {
            o_hf[i] = g_h_all[(size_t)T_STEPS * B * H + i];
            o_cf[i] = g_c_all[(size_t)T_STEPS * B * H + i];
        }
    }
}

// ---------------- host launcher ----------------
extern "C" void kernel_launch(void* const* d_in, const int* in_sizes, int n_in,
                              void* d_out, int out_size) {
    const float* dec_in = (const float*)d_in[0];
    const float* h0     = (const float*)d_in[1];
    const float* c0     = (const float*)d_in[2];
    const float* enc    = (const float*)d_in[3];
    const float* mask   = (const float*)d_in[4];
    const float* Wh     = (const float*)d_in[5];
    const float* bh     = (const float*)d_in[6];
    const float* Ws_    = (const float*)d_in[7];
    const float* bs_    = (const float*)d_in[8];
    const float* v      = (const float*)d_in[9];
    const float* Wx     = (const float*)d_in[10];
    const float* bx     = (const float*)d_in[11];
    const float* Wih    = (const float*)d_in[12];
    const float* bih    = (const float*)d_in[13];
    const float* Whh    = (const float*)d_in[14];
    const float* bhh    = (const float*)d_in[15];
    const float* Wpg    = (const float*)d_in[16];
    const float* bpg    = (const float*)d_in[17];
    const float* Wout   = (const float*)d_in[18];
    const float* bout   = (const float*)d_in[19];

    float* out = (float*)d_out;
    float* o_outputs = out;                                  // [T,B,H]
    float* o_hf = o_outputs + (size_t)T_STEPS * B * H;       // [B,H]
    float* o_cf = o_hf + B * H;                              // [B,H]
    float* o_attn = o_cf + B * H;                            // [T,B,L]
    float* o_pgen = o_attn + (size_t)T_STEPS * B * L;        // [T,B,1]

    k_prep<<<2384, 256>>>(Wh, Ws_, Wout, Wih, Wx, h0, c0);
    k_xg<<<dim3(2, 25), 256>>>(dec_in, bx);
    k_gig<<<dim3(16, 25), 256>>>(bih, bhh);

    k_fat<<<CHAIN_BLOCKS + 1024, 256>>>(Whh, enc, bh);

    k_dec_gemm<<<dim3(4, 25), 256>>>(bs_);
    k_escore_all<<<4096, 256>>>(v);
    k_softmax_all<<<1600, 256>>>(mask, o_attn);
    k_ctx_gemm<<<dim3(8, 16), 256>>>(enc, o_attn);
    k_out_gemm<<<dim3(4, 25), 256>>>(bout, o_outputs);
    k_pgen<<<202, 256>>>(Wpg, bpg, o_pgen, o_hf, o_cf);
}

// round 12
// speedup vs baseline: 1.5974x; 1.0803x over previous
#include <cuda_runtime.h>
#include <cstdint>

#define T_STEPS 100
#define B 16
#define E 128
#define H 256
#define L 2048

// ---------------- device scratch (static allocations only) ----------------
__device__ float g_enc_feat[B * L * H];                 // holds Eexp = exp(2(ef+bh))
__device__ float g_WhT[512 * 256];
__device__ float g_WsT[512 * 256];
__device__ float g_WoutT[768 * 256];
__device__ float g_WihT[128 * 1024];
__device__ float g_WxT[128 * 128];
__device__ float g_x_all[T_STEPS * B * E];
__device__ float g_gi[T_STEPS * B * 4 * H];
__device__ float g_h_all[(T_STEPS + 1) * B * H];
__device__ float g_c_all[(T_STEPS + 1) * B * H];
__device__ float g_dec_all[T_STEPS * B * H];            // holds D = exp(2*dec)
__device__ float g_ctx_all[T_STEPS * B * 2 * H];
__device__ float g_e_tr[B * L * 128];                   // [b][l][t(pad128)]

#define L2E2 2.885390082f   // 2*log2(e)

// ---------------- fast math helpers ----------------
__device__ __forceinline__ float tanh_f(float x) {
    float e = __expf(2.f * x);
    return 1.f - __fdividef(2.f, e + 1.f);
}
__device__ __forceinline__ float sig_f(float x) {
    return __fdividef(1.f, 1.f + __expf(-x));
}
__device__ __forceinline__ float ex2(float x) {
    float r;
    asm("ex2.approx.ftz.f32 %0, %1;" : "=f"(r) : "f"(x));
    return r;
}
__device__ __forceinline__ float rcp(float x) {
    float r;
    asm("rcp.approx.ftz.f32 %0, %1;" : "=f"(r) : "f"(x));
    return r;
}
__device__ __forceinline__ float wreduce(float s) {
    #pragma unroll
    for (int off = 16; off; off >>= 1) s += __shfl_xor_sync(0xffffffffu, s, off);
    return s;
}
__device__ __forceinline__ float wmax(float s) {
    #pragma unroll
    for (int off = 16; off; off >>= 1) s = fmaxf(s, __shfl_xor_sync(0xffffffffu, s, off));
    return s;
}
__device__ __forceinline__ unsigned long long pack2(float x, float y) {
    unsigned long long r;
    asm("mov.b64 %0, {%1, %2};" : "=l"(r) : "f"(x), "f"(y));
    return r;
}
__device__ __forceinline__ void fma2(unsigned long long& d, unsigned long long a, unsigned long long b) {
    asm("fma.rn.f32x2 %0, %1, %2, %3;" : "=l"(d) : "l"(a), "l"(b), "l"(d));
}
__device__ __forceinline__ float2 unpack2(unsigned long long v) {
    float2 f;
    asm("mov.b64 {%0, %1}, %2;" : "=f"(f.x), "=f"(f.y) : "l"(v));
    return f;
}
__device__ __forceinline__ uint32_t smem_u32(const void* p) {
    uint32_t a;
    asm("{ .reg .u64 t; cvta.to.shared.u64 t, %1; cvt.u32.u64 %0, t; }" : "=r"(a) : "l"(p));
    return a;
}
__device__ __forceinline__ float dsmem_ld(uint32_t local_addr, uint32_t rank) {
    uint32_t ra;
    asm("mapa.shared::cluster.u32 %0, %1, %2;" : "=r"(ra) : "r"(local_addr), "r"(rank));
    float v;
    asm volatile("ld.shared::cluster.f32 %0, [%1];" : "=f"(v) : "r"(ra));
    return v;
}

// ---------------- prep: all transposes + h/c init --------------------------
__global__ void k_prep(const float* __restrict__ Wh, const float* __restrict__ Ws_,
                       const float* __restrict__ Wout, const float* __restrict__ Wih,
                       const float* __restrict__ Wx,
                       const float* __restrict__ h0, const float* __restrict__ c0) {
    int blk = blockIdx.x, tid = threadIdx.x;
    if (blk < 512) {
        int i = blk * 256 + tid;
        int j = i & 255, k = i >> 8;
        g_WhT[i] = Wh[j * 512 + k];
    } else if (blk < 1024) {
        int i = (blk - 512) * 256 + tid;
        int j = i & 255, k = i >> 8;
        g_WsT[i] = Ws_[j * 512 + k];
    } else if (blk < 1792) {
        int i = (blk - 1024) * 256 + tid;
        int j = i & 255, k = i >> 8;
        g_WoutT[i] = Wout[j * 768 + k];
    } else if (blk < 2304) {
        int i = (blk - 1792) * 256 + tid;
        int j = i & 1023, k = i >> 10;
        g_WihT[i] = Wih[j * 128 + k];
    } else if (blk < 2368) {
        int i = (blk - 2304) * 256 + tid;
        int j = i & 127, k = i >> 7;
        g_WxT[i] = Wx[j * (2 * H + E) + k];
    } else {
        int i = (blk - 2368) * 256 + tid;
        g_h_all[i] = h0[i];
        g_c_all[i] = c0[i];
    }
}

// ---------------- x GEMM: [1600,128] = dec_in @ WxT + bx -------------------
__global__ void __launch_bounds__(256)
k_xg(const float* __restrict__ Din, const float* __restrict__ bx) {
    __shared__ float As[64][17];
    __shared__ float Bs[16][64];
    const int m0 = blockIdx.y * 64;
    const int n0 = blockIdx.x * 64;
    const int tid = threadIdx.x;
    const int tx = tid & 15, ty = tid >> 4;
    float acc[4][4] = {};
    for (int k0 = 0; k0 < 128; k0 += 16) {
        for (int i = tid; i < 64 * 16; i += 256) {
            int m = i >> 4, k = i & 15;
            As[m][k] = Din[(size_t)(m0 + m) * 128 + k0 + k];
        }
        for (int i = tid; i < 16 * 64; i += 256) {
            int k = i >> 6, n = i & 63;
            Bs[k][n] = g_WxT[(size_t)(k0 + k) * 128 + n0 + n];
        }
        __syncthreads();
        #pragma unroll
        for (int kk = 0; kk < 16; kk++) {
            float a0 = As[ty * 4 + 0][kk], a1 = As[ty * 4 + 1][kk];
            float a2 = As[ty * 4 + 2][kk], a3 = As[ty * 4 + 3][kk];
            float4 b4 = *(const float4*)&Bs[kk][tx * 4];
            acc[0][0] += a0 * b4.x; acc[0][1] += a0 * b4.y; acc[0][2] += a0 * b4.z; acc[0][3] += a0 * b4.w;
            acc[1][0] += a1 * b4.x; acc[1][1] += a1 * b4.y; acc[1][2] += a1 * b4.z; acc[1][3] += a1 * b4.w;
            acc[2][0] += a2 * b4.x; acc[2][1] += a2 * b4.y; acc[2][2] += a2 * b4.z; acc[2][3] += a2 * b4.w;
            acc[3][0] += a3 * b4.x; acc[3][1] += a3 * b4.y; acc[3][2] += a3 * b4.z; acc[3][3] += a3 * b4.w;
        }
        __syncthreads();
    }
    #pragma unroll
    for (int i = 0; i < 4; i++) {
        int r = m0 + ty * 4 + i;
        #pragma unroll
        for (int j = 0; j < 4; j++) {
            int n = n0 + tx * 4 + j;
            g_x_all[(size_t)r * 128 + n] = acc[i][j] + bx[n];
        }
    }
}

// ---------------- gi GEMM: [1600,1024] = x_all @ WihT + bih + bhh ----------
__global__ void __launch_bounds__(256)
k_gig(const float* __restrict__ bih, const float* __restrict__ bhh) {
    __shared__ float As[64][17];
    __shared__ float Bs[16][64];
    const int m0 = blockIdx.y * 64;
    const int n0 = blockIdx.x * 64;
    const int tid = threadIdx.x;
    const int tx = tid & 15, ty = tid >> 4;
    float acc[4][4] = {};
    for (int k0 = 0; k0 < 128; k0 += 16) {
        for (int i = tid; i < 64 * 16; i += 256) {
            int m = i >> 4, k = i & 15;
            As[m][k] = g_x_all[(size_t)(m0 + m) * 128 + k0 + k];
        }
        for (int i = tid; i < 16 * 64; i += 256) {
            int k = i >> 6, n = i & 63;
            Bs[k][n] = g_WihT[(size_t)(k0 + k) * 1024 + n0 + n];
        }
        __syncthreads();
        #pragma unroll
        for (int kk = 0; kk < 16; kk++) {
            float a0 = As[ty * 4 + 0][kk], a1 = As[ty * 4 + 1][kk];
            float a2 = As[ty * 4 + 2][kk], a3 = As[ty * 4 + 3][kk];
            float4 b4 = *(const float4*)&Bs[kk][tx * 4];
            acc[0][0] += a0 * b4.x; acc[0][1] += a0 * b4.y; acc[0][2] += a0 * b4.z; acc[0][3] += a0 * b4.w;
            acc[1][0] += a1 * b4.x; acc[1][1] += a1 * b4.y; acc[1][2] += a1 * b4.z; acc[1][3] += a1 * b4.w;
            acc[2][0] += a2 * b4.x; acc[2][1] += a2 * b4.y; acc[2][2] += a2 * b4.z; acc[2][3] += a2 * b4.w;
            acc[3][0] += a3 * b4.x; acc[3][1] += a3 * b4.y; acc[3][2] += a3 * b4.z; acc[3][3] += a3 * b4.w;
        }
        __syncthreads();
    }
    #pragma unroll
    for (int i = 0; i < 4; i++) {
        int r = m0 + ty * 4 + i;
        #pragma unroll
        for (int j = 0; j < 4; j++) {
            int n = n0 + tx * 4 + j;
            g_gi[(size_t)r * 1024 + n] = acc[i][j] + bih[n] + bhh[n];
        }
    }
}

// ---------------- enc_feat GEMM (standalone): stores Eexp ------------------
__global__ void __launch_bounds__(256)
k_encfeat2(const float* __restrict__ ES, const float* __restrict__ bh) {
    __shared__ __align__(16) float Ast[16][132];
    __shared__ __align__(16) float Bs[16][64];
    const int tid = threadIdx.x;
    const int m0 = blockIdx.y * 128;
    const int n0 = blockIdx.x * 64;
    const int tx = tid & 15, ty = tid >> 4;
    unsigned long long acc[4][4];
    #pragma unroll
    for (int p = 0; p < 4; p++)
        #pragma unroll
        for (int n = 0; n < 4; n++) acc[p][n] = 0ull;

    for (int k0 = 0; k0 < 512; k0 += 16) {
        __syncthreads();
        #pragma unroll
        for (int u = 0; u < 2; u++) {
            int idx = u * 256 + tid;
            int row = idx >> 2, q = idx & 3;
            float4 f = *(const float4*)(ES + (size_t)(m0 + row) * 512 + k0 + q * 4);
            Ast[q * 4 + 0][row] = f.x;
            Ast[q * 4 + 1][row] = f.y;
            Ast[q * 4 + 2][row] = f.z;
            Ast[q * 4 + 3][row] = f.w;
        }
        {
            int kk = tid >> 4, n4 = (tid & 15) * 4;
            *(float4*)&Bs[kk][n4] = *(const float4*)(g_WhT + (size_t)(k0 + kk) * 256 + n0 + n4);
        }
        __syncthreads();
        #pragma unroll
        for (int kk = 0; kk < 16; kk++) {
            unsigned long long a2[4];
            #pragma unroll
            for (int p = 0; p < 4; p++)
                a2[p] = *(const unsigned long long*)&Ast[kk][ty * 8 + p * 2];
            float4 b4 = *(const float4*)&Bs[kk][tx * 4];
            unsigned long long bb[4];
            bb[0] = pack2(b4.x, b4.x); bb[1] = pack2(b4.y, b4.y);
            bb[2] = pack2(b4.z, b4.z); bb[3] = pack2(b4.w, b4.w);
            #pragma unroll
            for (int p = 0; p < 4; p++)
                #pragma unroll
                for (int n = 0; n < 4; n++)
                    fma2(acc[p][n], a2[p], bb[n]);
        }
    }
    #pragma unroll
    for (int p = 0; p < 4; p++) {
        int m = m0 + ty * 8 + p * 2;
        #pragma unroll
        for (int n = 0; n < 4; n++) {
            float2 f = unpack2(acc[p][n]);
            int col = n0 + tx * 4 + n;
            float bv = bh[col];
            g_enc_feat[(size_t)m * 256 + col] = ex2((f.x + bv) * L2E2);
            g_enc_feat[(size_t)(m + 1) * 256 + col] = ex2((f.y + bv) * L2E2);
        }
    }
}

// ================= cluster LSTM chain ======================================
// grid = 64 CTAs (8 clusters of 8), 512 threads. Cluster c owns batches
// {2c, 2c+1}. CTA rank r owns j in [r*32, r*32+32); warp w owns j = r*32+2w+{0,1}.
// Per step: compute gates -> export h slice to own smem -> barrier.cluster ->
// gather full h via ld.shared::cluster -> __syncthreads -> next step.
__global__ void __launch_bounds__(512, 1) __cluster_dims__(8, 1, 1)
k_chain2(const float* __restrict__ Whh) {
    __shared__ float h_loc[2][H];       // full h for the 2 batches
    __shared__ float c_loc[2][32];      // c for this CTA's j-range
    __shared__ float exp_h[2][64];      // export [parity][b*32 + jl]
    const int tid = threadIdx.x;
    const int lane = tid & 31, wid = tid >> 5;   // wid 0..15
    uint32_t rank;
    asm("mov.u32 %0, %%cluster_ctarank;" : "=r"(rank));
    const int b0 = (blockIdx.x >> 3) * 2;
    const int jbase = (int)rank * 32 + wid * 2;

    // weights resident: w[jq][g][i] over k = lane + 32*i
    float w[2][4][8];
    #pragma unroll
    for (int jq = 0; jq < 2; jq++)
        #pragma unroll
        for (int g = 0; g < 4; g++)
            #pragma unroll
            for (int i = 0; i < 8; i++)
                w[jq][g][i] = Whh[(size_t)(g * H + jbase + jq) * H + lane + 32 * i];

    // init h(0), c(0)
    {
        int b = tid >> 8, j = tid & 255;
        h_loc[b][j] = g_h_all[(b0 + b) * H + j];
        if (tid < 64)
            c_loc[tid >> 5][tid & 31] = g_c_all[(b0 + (tid >> 5)) * H + (int)rank * 32 + (tid & 31)];
    }
    __syncthreads();

    const int gb = tid >> 8;            // gather: batch of this thread
    const int gj = tid & 255;           // gather: j of this thread
    const uint32_t gowner = (uint32_t)(gj >> 5);

    for (int t = 0; t < T_STEPS; t++) {
        const int par = t & 1;

        // 16 dots, butterfly reduce (result in all lanes)
        float res[2][2][4];
        #pragma unroll
        for (int jq = 0; jq < 2; jq++)
            #pragma unroll
            for (int bq = 0; bq < 2; bq++) {
                const float* hb = h_loc[bq];
                #pragma unroll
                for (int g = 0; g < 4; g++) {
                    float s = 0.f;
                    #pragma unroll
                    for (int i = 0; i < 8; i++) s += w[jq][g][i] * hb[lane + 32 * i];
                    res[jq][bq][g] = wreduce(s);
                }
            }

        // pointwise: lanes 0-3 handle combos (jq = lane>>1, bq = lane&1)
        if (lane < 4) {
            const int jq = lane >> 1, bq = lane & 1;
            float rg[4];
            #pragma unroll
            for (int g = 0; g < 4; g++) {
                float a = (lane & 1) ? res[0][1][g] : res[0][0][g];
                float c2 = (lane & 1) ? res[1][1][g] : res[1][0][g];
                rg[g] = (lane >= 2) ? c2 : a;
            }
            const int j = jbase + jq;
            const int jl = wid * 2 + jq;
            const float* gi = g_gi + (size_t)(t * B + b0 + bq) * 1024;
            float ig = rg[0] + gi[j];
            float fg = rg[1] + gi[256 + j];
            float gg = rg[2] + gi[512 + j];
            float og = rg[3] + gi[768 + j];
            float cold = c_loc[bq][jl];
            float cn = sig_f(fg) * cold + sig_f(ig) * tanh_f(gg);
            float hn = sig_f(og) * tanh_f(cn);
            c_loc[bq][jl] = cn;
            exp_h[par][bq * 32 + jl] = hn;
            g_h_all[(size_t)(t + 1) * B * H + (b0 + bq) * H + j] = hn;
            g_c_all[(size_t)(t + 1) * B * H + (b0 + bq) * H + j] = cn;
        }

        // cluster barrier: releases exports, then gather full h
        asm volatile("barrier.cluster.arrive.aligned;" ::: "memory");
        asm volatile("barrier.cluster.wait.aligned;" ::: "memory");

        {
            uint32_t laddr = smem_u32(&exp_h[par][gb * 32 + (gj & 31)]);
            float hv = dsmem_ld(laddr, gowner);
            h_loc[gb][gj] = hv;
        }
        __syncthreads();
    }

    // protect peer smem until all cluster CTAs done
    asm volatile("barrier.cluster.arrive.aligned;" ::: "memory");
    asm volatile("barrier.cluster.wait.aligned;" ::: "memory");
}

// ---------------- dec_feat batched GEMM → stores D = exp(2*dec) ------------
__global__ void __launch_bounds__(256)
k_dec_gemm(const float* __restrict__ bs_) {
    __shared__ float As[64][17];
    __shared__ float Bs[16][64];
    const int m0 = blockIdx.y * 64;
    const int n0 = blockIdx.x * 64;
    const int tid = threadIdx.x;
    const int tx = tid & 15, ty = tid >> 4;
    float acc[4][4] = {};
    for (int k0 = 0; k0 < 512; k0 += 16) {
        for (int i = tid; i < 64 * 16; i += 256) {
            int m = i >> 4, k = i & 15;
            int r = m0 + m;
            int t = r >> 4, bb = r & 15;
            int kk = k0 + k;
            float v = (kk < 256)
                ? g_h_all[(size_t)(t + 1) * B * H + bb * H + kk]
                : g_c_all[(size_t)(t + 1) * B * H + bb * H + kk - 256];
            As[m][k] = v;
        }
        for (int i = tid; i < 16 * 64; i += 256) {
            int k = i >> 6, n = i & 63;
            Bs[k][n] = g_WsT[(size_t)(k0 + k) * 256 + n0 + n];
        }
        __syncthreads();
        #pragma unroll
        for (int kk = 0; kk < 16; kk++) {
            float a0 = As[ty * 4 + 0][kk], a1 = As[ty * 4 + 1][kk];
            float a2 = As[ty * 4 + 2][kk], a3 = As[ty * 4 + 3][kk];
            float4 b4 = *(const float4*)&Bs[kk][tx * 4];
            acc[0][0] += a0 * b4.x; acc[0][1] += a0 * b4.y; acc[0][2] += a0 * b4.z; acc[0][3] += a0 * b4.w;
            acc[1][0] += a1 * b4.x; acc[1][1] += a1 * b4.y; acc[1][2] += a1 * b4.z; acc[1][3] += a1 * b4.w;
            acc[2][0] += a2 * b4.x; acc[2][1] += a2 * b4.y; acc[2][2] += a2 * b4.z; acc[2][3] += a2 * b4.w;
            acc[3][0] += a3 * b4.x; acc[3][1] += a3 * b4.y; acc[3][2] += a3 * b4.z; acc[3][3] += a3 * b4.w;
        }
        __syncthreads();
    }
    #pragma unroll
    for (int i = 0; i < 4; i++) {
        int r = m0 + ty * 4 + i;
        #pragma unroll
        for (int j = 0; j < 4; j++) {
            int n = n0 + tx * 4 + j;
            g_dec_all[(size_t)r * 256 + n] = ex2((acc[i][j] + bs_[n]) * L2E2);
        }
    }
}

// ---------------- batched e-scores: warp per (b,l), loop t -----------------
__global__ void __launch_bounds__(256)
k_escore_all(const float* __restrict__ v) {
    const int tid = threadIdx.x;
    const int lane = tid & 31, wid = tid >> 5;
    const int gwarp = blockIdx.x * 8 + wid;
    const int b = gwarp >> 11;
    const int l = gwarp & 2047;

    const float4* ef4 = (const float4*)(g_enc_feat + ((size_t)(b * L + l)) * H);
    const float4* v4 = (const float4*)v;
    float4 Ea = ef4[lane * 2], Eb = ef4[lane * 2 + 1];
    float4 va = v4[lane * 2], vb = v4[lane * 2 + 1];
    float Vtot = wreduce(va.x + va.y + va.z + va.w + vb.x + vb.y + vb.z + vb.w);
    float4 w2a = make_float4(2.f * va.x, 2.f * va.y, 2.f * va.z, 2.f * va.w);
    float4 w2b = make_float4(2.f * vb.x, 2.f * vb.y, 2.f * vb.z, 2.f * vb.w);

    float* eout = g_e_tr + ((size_t)(b * L + l)) * 128;

    #pragma unroll 1
    for (int c = 0; c < 4; c++) {
        float ereg = 0.f;
        int tmax = T_STEPS - c * 32;
        if (tmax > 32) tmax = 32;
        #pragma unroll 1
        for (int tt = 0; tt < tmax; tt++) {
            int t = c * 32 + tt;
            const float4* d4 = (const float4*)(g_dec_all + (size_t)(t * B + b) * H);
            float4 Da = d4[lane * 2], Db = d4[lane * 2 + 1];
            float A0 = fmaf(Ea.x, Da.x, 1.f);
            float A1 = fmaf(Ea.y, Da.y, 1.f);
            float A2 = fmaf(Ea.z, Da.z, 1.f);
            float A3 = fmaf(Ea.w, Da.w, 1.f);
            float A4 = fmaf(Eb.x, Db.x, 1.f);
            float A5 = fmaf(Eb.y, Db.y, 1.f);
            float A6 = fmaf(Eb.z, Db.z, 1.f);
            float A7 = fmaf(Eb.w, Db.w, 1.f);
            float acc = w2a.x * rcp(A0);
            acc = fmaf(w2a.y, rcp(A1), acc);
            acc = fmaf(w2a.z, rcp(A2), acc);
            acc = fmaf(w2a.w, rcp(A3), acc);
            acc = fmaf(w2b.x, rcp(A4), acc);
            acc = fmaf(w2b.y, rcp(A5), acc);
            acc = fmaf(w2b.z, rcp(A6), acc);
            acc = fmaf(w2b.w, rcp(A7), acc);
            float s = Vtot - wreduce(acc);
            if (tt == lane) ereg = s;
        }
        if (c * 32 + lane < T_STEPS) eout[c * 32 + lane] = ereg;
    }
}

// ---------------- batched softmax: block per (t,b) -------------------------
__global__ void __launch_bounds__(256)
k_softmax_all(const float* __restrict__ mask, float* __restrict__ o_attn) {
    __shared__ float red[16];
    const int r = blockIdx.x;
    const int t = r >> 4, b = r & 15;
    const int tid = threadIdx.x;
    const int lane = tid & 31, wid = tid >> 5;

    const float* mrow = mask + (size_t)b * L;

    float ev[8], mv[8];
    float mx = -3.4e38f;
    #pragma unroll
    for (int i = 0; i < 8; i++) {
        int l = tid + i * 256;
        ev[i] = g_e_tr[((size_t)(b * L + l)) * 128 + t];
        mv[i] = mrow[l];
        mx = fmaxf(mx, ev[i]);
    }
    mx = wmax(mx);
    if (lane == 0) red[wid] = mx;
    __syncthreads();
    mx = red[0];
    #pragma unroll
    for (int i = 1; i < 8; i++) mx = fmaxf(mx, red[i]);

    float pv[8];
    float s = 0.f;
    #pragma unroll
    for (int i = 0; i < 8; i++) {
        pv[i] = __expf(ev[i] - mx) * mv[i];
        s += pv[i];
    }
    s = wreduce(s);
    if (lane == 0) red[8 + wid] = s;
    __syncthreads();
    s = 0.f;
    #pragma unroll
    for (int i = 0; i < 8; i++) s += red[8 + i];
    float inv = __fdividef(1.f, s);
    #pragma unroll
    for (int i = 0; i < 8; i++)
        o_attn[(size_t)r * L + tid + i * 256] = pv[i] * inv;
}

// ---------------- ctx batched GEMM per b: [128(t),2048]x[2048,512] ---------
__global__ void __launch_bounds__(256)
k_ctx_gemm(const float* __restrict__ enc, const float* __restrict__ o_attn) {
    __shared__ __align__(16) float Ast[16][132];
    __shared__ __align__(16) float Bs[16][64];
    const int tid = threadIdx.x;
    const int b = blockIdx.y;
    const int n0 = blockIdx.x * 64;
    const int tx = tid & 15, ty = tid >> 4;
    unsigned long long acc[4][4];
    #pragma unroll
    for (int p = 0; p < 4; p++)
        #pragma unroll
        for (int n = 0; n < 4; n++) acc[p][n] = 0ull;

    for (int k0 = 0; k0 < L; k0 += 16) {
        __syncthreads();
        #pragma unroll
        for (int u = 0; u < 2; u++) {
            int idx = u * 256 + tid;
            int row = idx >> 2, q = idx & 3;
            float4 f = make_float4(0.f, 0.f, 0.f, 0.f);
            if (row < T_STEPS)
                f = *(const float4*)(o_attn + ((size_t)(row * B + b)) * L + k0 + q * 4);
            Ast[q * 4 + 0][row] = f.x;
            Ast[q * 4 + 1][row] = f.y;
            Ast[q * 4 + 2][row] = f.z;
            Ast[q * 4 + 3][row] = f.w;
        }
        {
            int kk = tid >> 4, n4 = (tid & 15) * 4;
            *(float4*)&Bs[kk][n4] =
                *(const float4*)(enc + ((size_t)(b * L + k0 + kk)) * (2 * H) + n0 + n4);
        }
        __syncthreads();
        #pragma unroll
        for (int kk = 0; kk < 16; kk++) {
            unsigned long long a2[4];
            #pragma unroll
            for (int p = 0; p < 4; p++)
                a2[p] = *(const unsigned long long*)&Ast[kk][ty * 8 + p * 2];
            float4 b4 = *(const float4*)&Bs[kk][tx * 4];
            unsigned long long bb[4];
            bb[0] = pack2(b4.x, b4.x); bb[1] = pack2(b4.y, b4.y);
            bb[2] = pack2(b4.z, b4.z); bb[3] = pack2(b4.w, b4.w);
            #pragma unroll
            for (int p = 0; p < 4; p++)
                #pragma unroll
                for (int n = 0; n < 4; n++)
                    fma2(acc[p][n], a2[p], bb[n]);
        }
    }
    #pragma unroll
    for (int p = 0; p < 4; p++) {
        int t = ty * 8 + p * 2;
        #pragma unroll
        for (int n = 0; n < 4; n++) {
            float2 f = unpack2(acc[p][n]);
            int col = n0 + tx * 4 + n;
            if (t < T_STEPS)
                g_ctx_all[(size_t)(t * B + b) * (2 * H) + col] = f.x;
            if (t + 1 < T_STEPS)
                g_ctx_all[(size_t)((t + 1) * B + b) * (2 * H) + col] = f.y;
        }
    }
}

// ---------------- out batched GEMM: [1600,768]x[768,256] -------------------
__global__ void __launch_bounds__(256)
k_out_gemm(const float* __restrict__ bout, float* __restrict__ o_out) {
    __shared__ float As[64][17];
    __shared__ float Bs[16][64];
    const int m0 = blockIdx.y * 64;
    const int n0 = blockIdx.x * 64;
    const int tid = threadIdx.x;
    const int tx = tid & 15, ty = tid >> 4;
    float acc[4][4] = {};
    for (int k0 = 0; k0 < 768; k0 += 16) {
        for (int i = tid; i < 64 * 16; i += 256) {
            int m = i >> 4, k = i & 15;
            int r = m0 + m;
            int t = r >> 4, bb = r & 15;
            int kk = k0 + k;
            float v = (kk < 256)
                ? g_h_all[(size_t)(t + 1) * B * H + bb * H + kk]
                : g_ctx_all[(size_t)r * 512 + kk - 256];
            As[m][k] = v;
        }
        for (int i = tid; i < 16 * 64; i += 256) {
            int k = i >> 6, n = i & 63;
            Bs[k][n] = g_WoutT[(size_t)(k0 + k) * 256 + n0 + n];
        }
        __syncthreads();
        #pragma unroll
        for (int kk = 0; kk < 16; kk++) {
            float a0 = As[ty * 4 + 0][kk], a1 = As[ty * 4 + 1][kk];
            float a2 = As[ty * 4 + 2][kk], a3 = As[ty * 4 + 3][kk];
            float4 b4 = *(const float4*)&Bs[kk][tx * 4];
            acc[0][0] += a0 * b4.x; acc[0][1] += a0 * b4.y; acc[0][2] += a0 * b4.z; acc[0][3] += a0 * b4.w;
            acc[1][0] += a1 * b4.x; acc[1][1] += a1 * b4.y; acc[1][2] += a1 * b4.z; acc[1][3] += a1 * b4.w;
            acc[2][0] += a2 * b4.x; acc[2][1] += a2 * b4.y; acc[2][2] += a2 * b4.z; acc[2][3] += a2 * b4.w;
            acc[3][0] += a3 * b4.x; acc[3][1] += a3 * b4.y; acc[3][2] += a3 * b4.z; acc[3][3] += a3 * b4.w;
        }
        __syncthreads();
    }
    #pragma unroll
    for (int i = 0; i < 4; i++) {
        int r = m0 + ty * 4 + i;
        #pragma unroll
        for (int j = 0; j < 4; j++) {
            int n = n0 + tx * 4 + j;
            o_out[(size_t)r * 256 + n] = acc[i][j] + bout[n];
        }
    }
}

// ---------------- p_gen batched + h_f/c_f ----------------------------------
__global__ void __launch_bounds__(256)
k_pgen(const float* __restrict__ Wpg, const float* __restrict__ bpg,
       float* __restrict__ o_pgen, float* __restrict__ o_hf, float* __restrict__ o_cf) {
    const int tid = threadIdx.x;
    const int lane = tid & 31, wid = tid >> 5;
    const int blk = blockIdx.x;

    if (blk < 200) {
        const int r = blk * 8 + wid;
        const int t = r >> 4, bb = r & 15;
        float s = 0.f;
        for (int k = lane; k < 4 * H + E; k += 32) {
            float cv;
            if (k < 2 * H) cv = g_ctx_all[(size_t)r * 512 + k];
            else if (k < 3 * H) cv = g_h_all[(size_t)(t + 1) * B * H + bb * H + k - 2 * H];
            else if (k < 4 * H) cv = g_c_all[(size_t)(t + 1) * B * H + bb * H + k - 3 * H];
            else cv = g_x_all[(size_t)r * E + k - 4 * H];
            s += cv * Wpg[k];
        }
        s = wreduce(s);
        if (lane == 0) o_pgen[r] = sig_f(s + bpg[0]);
    } else {
        for (int i = (blk - 200) * 256 + tid; i < B * H; i += 512) {
            o_hf[i] = g_h_all[(size_t)T_STEPS * B * H + i];
            o_cf[i] = g_c_all[(size_t)T_STEPS * B * H + i];
        }
    }
}

// ---------------- host launcher ----------------
extern "C" void kernel_launch(void* const* d_in, const int* in_sizes, int n_in,
                              void* d_out, int out_size) {
    const float* dec_in = (const float*)d_in[0];
    const float* h0     = (const float*)d_in[1];
    const float* c0     = (const float*)d_in[2];
    const float* enc    = (const float*)d_in[3];
    const float* mask   = (const float*)d_in[4];
    const float* Wh     = (const float*)d_in[5];
    const float* bh     = (const float*)d_in[6];
    const float* Ws_    = (const float*)d_in[7];
    const float* bs_    = (const float*)d_in[8];
    const float* v      = (const float*)d_in[9];
    const float* Wx     = (const float*)d_in[10];
    const float* bx     = (const float*)d_in[11];
    const float* Wih    = (const float*)d_in[12];
    const float* bih    = (const float*)d_in[13];
    const float* Whh    = (const float*)d_in[14];
    const float* bhh    = (const float*)d_in[15];
    const float* Wpg    = (const float*)d_in[16];
    const float* bpg    = (const float*)d_in[17];
    const float* Wout   = (const float*)d_in[18];
    const float* bout   = (const float*)d_in[19];

    float* out = (float*)d_out;
    float* o_outputs = out;                                  // [T,B,H]
    float* o_hf = o_outputs + (size_t)T_STEPS * B * H;       // [B,H]
    float* o_cf = o_hf + B * H;                              // [B,H]
    float* o_attn = o_cf + B * H;                            // [T,B,L]
    float* o_pgen = o_attn + (size_t)T_STEPS * B * L;        // [T,B,1]

    k_prep<<<2384, 256>>>(Wh, Ws_, Wout, Wih, Wx, h0, c0);
    k_xg<<<dim3(2, 25), 256>>>(dec_in, bx);
    k_gig<<<dim3(16, 25), 256>>>(bih, bhh);

    k_chain2<<<64, 512>>>(Whh);
    k_encfeat2<<<dim3(4, 256), 256>>>(enc, bh);

    k_dec_gemm<<<dim3(4, 25), 256>>>(bs_);
    k_escore_all<<<4096, 256>>>(v);
    k_softmax_all<<<1600, 256>>>(mask, o_attn);
    k_ctx_gemm<<<dim3(8, 16), 256>>>(enc, o_attn);
    k_out_gemm<<<dim3(4, 25), 256>>>(bout, o_outputs);
    k_pgen<<<202, 256>>>(Wpg, bpg, o_pgen, o_hf, o_cf);
}

// round 13
// speedup vs baseline: 1.6690x; 1.0448x over previous
#include <cuda_runtime.h>
#include <cstdint>

#define T_STEPS 100
#define B 16
#define E 128
#define H 256
#define L 2048

// ---------------- device scratch (static allocations only) ----------------
__device__ float g_enc_feat[B * L * H];                 // holds Eexp = exp(2(ef+bh))
__device__ float g_WhT[512 * 256];
__device__ float g_WsT[512 * 256];
__device__ float g_WoutT[768 * 256];
__device__ float g_WihT[128 * 1024];
__device__ float g_WxT[128 * 128];
__device__ float g_x_all[T_STEPS * B * E];
__device__ float g_gi[T_STEPS * B * 4 * H];
__device__ float g_h_all[(T_STEPS + 1) * B * H];
__device__ float g_c_all[(T_STEPS + 1) * B * H];
__device__ float g_dec_all[T_STEPS * B * H];            // holds D = exp(2*dec)
__device__ float g_ctx_all[T_STEPS * B * 2 * H];
__device__ float g_e_tr[B * L * 128];                   // [b][l][t(pad128)]

#define L2E2 2.885390082f   // 2*log2(e)

// ---------------- fast math helpers ----------------
__device__ __forceinline__ float tanh_f(float x) {
    float e = __expf(2.f * x);
    return 1.f - __fdividef(2.f, e + 1.f);
}
__device__ __forceinline__ float sig_f(float x) {
    return __fdividef(1.f, 1.f + __expf(-x));
}
__device__ __forceinline__ float ex2(float x) {
    float r;
    asm("ex2.approx.ftz.f32 %0, %1;" : "=f"(r) : "f"(x));
    return r;
}
__device__ __forceinline__ float rcp(float x) {
    float r;
    asm("rcp.approx.ftz.f32 %0, %1;" : "=f"(r) : "f"(x));
    return r;
}
__device__ __forceinline__ float wreduce(float s) {
    #pragma unroll
    for (int off = 16; off; off >>= 1) s += __shfl_xor_sync(0xffffffffu, s, off);
    return s;
}
__device__ __forceinline__ float wmax(float s) {
    #pragma unroll
    for (int off = 16; off; off >>= 1) s = fmaxf(s, __shfl_xor_sync(0xffffffffu, s, off));
    return s;
}
__device__ __forceinline__ unsigned long long pack2(float x, float y) {
    unsigned long long r;
    asm("mov.b64 %0, {%1, %2};" : "=l"(r) : "f"(x), "f"(y));
    return r;
}
__device__ __forceinline__ void fma2(unsigned long long& d, unsigned long long a, unsigned long long b) {
    asm("fma.rn.f32x2 %0, %1, %2, %3;" : "=l"(d) : "l"(a), "l"(b), "l"(d));
}
__device__ __forceinline__ float2 unpack2(unsigned long long v) {
    float2 f;
    asm("mov.b64 {%0, %1}, %2;" : "=f"(f.x), "=f"(f.y) : "l"(v));
    return f;
}
__device__ __forceinline__ uint32_t smem_u32(const void* p) {
    uint32_t a;
    asm("{ .reg .u64 t; cvta.to.shared.u64 t, %1; cvt.u32.u64 %0, t; }" : "=r"(a) : "l"(p));
    return a;
}
__device__ __forceinline__ float dsmem_ld(uint32_t local_addr, uint32_t rank) {
    uint32_t ra;
    asm("mapa.shared::cluster.u32 %0, %1, %2;" : "=r"(ra) : "r"(local_addr), "r"(rank));
    float v;
    asm volatile("ld.shared::cluster.f32 %0, [%1];" : "=f"(v) : "r"(ra));
    return v;
}

// ---------------- prep: all transposes + h/c init --------------------------
__global__ void k_prep(const float* __restrict__ Wh, const float* __restrict__ Ws_,
                       const float* __restrict__ Wout, const float* __restrict__ Wih,
                       const float* __restrict__ Wx,
                       const float* __restrict__ h0, const float* __restrict__ c0) {
    int blk = blockIdx.x, tid = threadIdx.x;
    if (blk < 512) {
        int i = blk * 256 + tid;
        int j = i & 255, k = i >> 8;
        g_WhT[i] = Wh[j * 512 + k];
    } else if (blk < 1024) {
        int i = (blk - 512) * 256 + tid;
        int j = i & 255, k = i >> 8;
        g_WsT[i] = Ws_[j * 512 + k];
    } else if (blk < 1792) {
        int i = (blk - 1024) * 256 + tid;
        int j = i & 255, k = i >> 8;
        g_WoutT[i] = Wout[j * 768 + k];
    } else if (blk < 2304) {
        int i = (blk - 1792) * 256 + tid;
        int j = i & 1023, k = i >> 10;
        g_WihT[i] = Wih[j * 128 + k];
    } else if (blk < 2368) {
        int i = (blk - 2304) * 256 + tid;
        int j = i & 127, k = i >> 7;
        g_WxT[i] = Wx[j * (2 * H + E) + k];
    } else {
        int i = (blk - 2368) * 256 + tid;
        g_h_all[i] = h0[i];
        g_c_all[i] = c0[i];
    }
}

// ---------------- x GEMM: [1600,128] = dec_in @ WxT + bx -------------------
__global__ void __launch_bounds__(256)
k_xg(const float* __restrict__ Din, const float* __restrict__ bx) {
    __shared__ float As[64][17];
    __shared__ float Bs[16][64];
    const int m0 = blockIdx.y * 64;
    const int n0 = blockIdx.x * 64;
    const int tid = threadIdx.x;
    const int tx = tid & 15, ty = tid >> 4;
    float acc[4][4] = {};
    for (int k0 = 0; k0 < 128; k0 += 16) {
        for (int i = tid; i < 64 * 16; i += 256) {
            int m = i >> 4, k = i & 15;
            As[m][k] = Din[(size_t)(m0 + m) * 128 + k0 + k];
        }
        for (int i = tid; i < 16 * 64; i += 256) {
            int k = i >> 6, n = i & 63;
            Bs[k][n] = g_WxT[(size_t)(k0 + k) * 128 + n0 + n];
        }
        __syncthreads();
        #pragma unroll
        for (int kk = 0; kk < 16; kk++) {
            float a0 = As[ty * 4 + 0][kk], a1 = As[ty * 4 + 1][kk];
            float a2 = As[ty * 4 + 2][kk], a3 = As[ty * 4 + 3][kk];
            float4 b4 = *(const float4*)&Bs[kk][tx * 4];
            acc[0][0] += a0 * b4.x; acc[0][1] += a0 * b4.y; acc[0][2] += a0 * b4.z; acc[0][3] += a0 * b4.w;
            acc[1][0] += a1 * b4.x; acc[1][1] += a1 * b4.y; acc[1][2] += a1 * b4.z; acc[1][3] += a1 * b4.w;
            acc[2][0] += a2 * b4.x; acc[2][1] += a2 * b4.y; acc[2][2] += a2 * b4.z; acc[2][3] += a2 * b4.w;
            acc[3][0] += a3 * b4.x; acc[3][1] += a3 * b4.y; acc[3][2] += a3 * b4.z; acc[3][3] += a3 * b4.w;
        }
        __syncthreads();
    }
    #pragma unroll
    for (int i = 0; i < 4; i++) {
        int r = m0 + ty * 4 + i;
        #pragma unroll
        for (int j = 0; j < 4; j++) {
            int n = n0 + tx * 4 + j;
            g_x_all[(size_t)r * 128 + n] = acc[i][j] + bx[n];
        }
    }
}

// ---------------- gi GEMM: [1600,1024] = x_all @ WihT + bih + bhh ----------
__global__ void __launch_bounds__(256)
k_gig(const float* __restrict__ bih, const float* __restrict__ bhh) {
    __shared__ float As[64][17];
    __shared__ float Bs[16][64];
    const int m0 = blockIdx.y * 64;
    const int n0 = blockIdx.x * 64;
    const int tid = threadIdx.x;
    const int tx = tid & 15, ty = tid >> 4;
    float acc[4][4] = {};
    for (int k0 = 0; k0 < 128; k0 += 16) {
        for (int i = tid; i < 64 * 16; i += 256) {
            int m = i >> 4, k = i & 15;
            As[m][k] = g_x_all[(size_t)(m0 + m) * 128 + k0 + k];
        }
        for (int i = tid; i < 16 * 64; i += 256) {
            int k = i >> 6, n = i & 63;
            Bs[k][n] = g_WihT[(size_t)(k0 + k) * 1024 + n0 + n];
        }
        __syncthreads();
        #pragma unroll
        for (int kk = 0; kk < 16; kk++) {
            float a0 = As[ty * 4 + 0][kk], a1 = As[ty * 4 + 1][kk];
            float a2 = As[ty * 4 + 2][kk], a3 = As[ty * 4 + 3][kk];
            float4 b4 = *(const float4*)&Bs[kk][tx * 4];
            acc[0][0] += a0 * b4.x; acc[0][1] += a0 * b4.y; acc[0][2] += a0 * b4.z; acc[0][3] += a0 * b4.w;
            acc[1][0] += a1 * b4.x; acc[1][1] += a1 * b4.y; acc[1][2] += a1 * b4.z; acc[1][3] += a1 * b4.w;
            acc[2][0] += a2 * b4.x; acc[2][1] += a2 * b4.y; acc[2][2] += a2 * b4.z; acc[2][3] += a2 * b4.w;
            acc[3][0] += a3 * b4.x; acc[3][1] += a3 * b4.y; acc[3][2] += a3 * b4.z; acc[3][3] += a3 * b4.w;
        }
        __syncthreads();
    }
    #pragma unroll
    for (int i = 0; i < 4; i++) {
        int r = m0 + ty * 4 + i;
        #pragma unroll
        for (int j = 0; j < 4; j++) {
            int n = n0 + tx * 4 + j;
            g_gi[(size_t)r * 1024 + n] = acc[i][j] + bih[n] + bhh[n];
        }
    }
}

// ---------------- enc_feat GEMM (side stream): stores Eexp -----------------
__global__ void __launch_bounds__(256)
k_encfeat2(const float* __restrict__ ES, const float* __restrict__ bh) {
    __shared__ __align__(16) float Ast[16][132];
    __shared__ __align__(16) float Bs[16][64];
    const int tid = threadIdx.x;
    const int m0 = blockIdx.y * 128;
    const int n0 = blockIdx.x * 64;
    const int tx = tid & 15, ty = tid >> 4;
    unsigned long long acc[4][4];
    #pragma unroll
    for (int p = 0; p < 4; p++)
        #pragma unroll
        for (int n = 0; n < 4; n++) acc[p][n] = 0ull;

    for (int k0 = 0; k0 < 512; k0 += 16) {
        __syncthreads();
        #pragma unroll
        for (int u = 0; u < 2; u++) {
            int idx = u * 256 + tid;
            int row = idx >> 2, q = idx & 3;
            float4 f = *(const float4*)(ES + (size_t)(m0 + row) * 512 + k0 + q * 4);
            Ast[q * 4 + 0][row] = f.x;
            Ast[q * 4 + 1][row] = f.y;
            Ast[q * 4 + 2][row] = f.z;
            Ast[q * 4 + 3][row] = f.w;
        }
        {
            int kk = tid >> 4, n4 = (tid & 15) * 4;
            *(float4*)&Bs[kk][n4] = *(const float4*)(g_WhT + (size_t)(k0 + kk) * 256 + n0 + n4);
        }
        __syncthreads();
        #pragma unroll
        for (int kk = 0; kk < 16; kk++) {
            unsigned long long a2[4];
            #pragma unroll
            for (int p = 0; p < 4; p++)
                a2[p] = *(const unsigned long long*)&Ast[kk][ty * 8 + p * 2];
            float4 b4 = *(const float4*)&Bs[kk][tx * 4];
            unsigned long long bb[4];
            bb[0] = pack2(b4.x, b4.x); bb[1] = pack2(b4.y, b4.y);
            bb[2] = pack2(b4.z, b4.z); bb[3] = pack2(b4.w, b4.w);
            #pragma unroll
            for (int p = 0; p < 4; p++)
                #pragma unroll
                for (int n = 0; n < 4; n++)
                    fma2(acc[p][n], a2[p], bb[n]);
        }
    }
    #pragma unroll
    for (int p = 0; p < 4; p++) {
        int m = m0 + ty * 8 + p * 2;
        #pragma unroll
        for (int n = 0; n < 4; n++) {
            float2 f = unpack2(acc[p][n]);
            int col = n0 + tx * 4 + n;
            float bv = bh[col];
            g_enc_feat[(size_t)m * 256 + col] = ex2((f.x + bv) * L2E2);
            g_enc_feat[(size_t)(m + 1) * 256 + col] = ex2((f.y + bv) * L2E2);
        }
    }
}

// ================= cluster LSTM chain ======================================
__global__ void __launch_bounds__(512, 1) __cluster_dims__(8, 1, 1)
k_chain2(const float* __restrict__ Whh) {
    __shared__ float h_loc[2][H];
    __shared__ float c_loc[2][32];
    __shared__ float exp_h[2][64];
    const int tid = threadIdx.x;
    const int lane = tid & 31, wid = tid >> 5;
    uint32_t rank;
    asm("mov.u32 %0, %%cluster_ctarank;" : "=r"(rank));
    const int b0 = (blockIdx.x >> 3) * 2;
    const int jbase = (int)rank * 32 + wid * 2;

    float w[2][4][8];
    #pragma unroll
    for (int jq = 0; jq < 2; jq++)
        #pragma unroll
        for (int g = 0; g < 4; g++)
            #pragma unroll
            for (int i = 0; i < 8; i++)
                w[jq][g][i] = Whh[(size_t)(g * H + jbase + jq) * H + lane + 32 * i];

    {
        int b = tid >> 8, j = tid & 255;
        h_loc[b][j] = g_h_all[(b0 + b) * H + j];
        if (tid < 64)
            c_loc[tid >> 5][tid & 31] = g_c_all[(b0 + (tid >> 5)) * H + (int)rank * 32 + (tid & 31)];
    }
    __syncthreads();

    const int gb = tid >> 8;
    const int gj = tid & 255;
    const uint32_t gowner = (uint32_t)(gj >> 5);

    for (int t = 0; t < T_STEPS; t++) {
        const int par = t & 1;

        float res[2][2][4];
        #pragma unroll
        for (int jq = 0; jq < 2; jq++)
            #pragma unroll
            for (int bq = 0; bq < 2; bq++) {
                const float* hb = h_loc[bq];
                #pragma unroll
                for (int g = 0; g < 4; g++) {
                    float s = 0.f;
                    #pragma unroll
                    for (int i = 0; i < 8; i++) s += w[jq][g][i] * hb[lane + 32 * i];
                    res[jq][bq][g] = wreduce(s);
                }
            }

        if (lane < 4) {
            const int jq = lane >> 1, bq = lane & 1;
            float rg[4];
            #pragma unroll
            for (int g = 0; g < 4; g++) {
                float a = (lane & 1) ? res[0][1][g] : res[0][0][g];
                float c2 = (lane & 1) ? res[1][1][g] : res[1][0][g];
                rg[g] = (lane >= 2) ? c2 : a;
            }
            const int j = jbase + jq;
            const int jl = wid * 2 + jq;
            const float* gi = g_gi + (size_t)(t * B + b0 + bq) * 1024;
            float ig = rg[0] + gi[j];
            float fg = rg[1] + gi[256 + j];
            float gg = rg[2] + gi[512 + j];
            float og = rg[3] + gi[768 + j];
            float cold = c_loc[bq][jl];
            float cn = sig_f(fg) * cold + sig_f(ig) * tanh_f(gg);
            float hn = sig_f(og) * tanh_f(cn);
            c_loc[bq][jl] = cn;
            exp_h[par][bq * 32 + jl] = hn;
            g_h_all[(size_t)(t + 1) * B * H + (b0 + bq) * H + j] = hn;
            g_c_all[(size_t)(t + 1) * B * H + (b0 + bq) * H + j] = cn;
        }

        asm volatile("barrier.cluster.arrive.aligned;" ::: "memory");
        asm volatile("barrier.cluster.wait.aligned;" ::: "memory");

        {
            uint32_t laddr = smem_u32(&exp_h[par][gb * 32 + (gj & 31)]);
            float hv = dsmem_ld(laddr, gowner);
            h_loc[gb][gj] = hv;
        }
        __syncthreads();
    }

    asm volatile("barrier.cluster.arrive.aligned;" ::: "memory");
    asm volatile("barrier.cluster.wait.aligned;" ::: "memory");
}

// ---------------- dec_feat batched GEMM → stores D = exp(2*dec) ------------
__global__ void __launch_bounds__(256)
k_dec_gemm(const float* __restrict__ bs_) {
    __shared__ float As[64][17];
    __shared__ float Bs[16][64];
    const int m0 = blockIdx.y * 64;
    const int n0 = blockIdx.x * 64;
    const int tid = threadIdx.x;
    const int tx = tid & 15, ty = tid >> 4;
    float acc[4][4] = {};
    for (int k0 = 0; k0 < 512; k0 += 16) {
        for (int i = tid; i < 64 * 16; i += 256) {
            int m = i >> 4, k = i & 15;
            int r = m0 + m;
            int t = r >> 4, bb = r & 15;
            int kk = k0 + k;
            float v = (kk < 256)
                ? g_h_all[(size_t)(t + 1) * B * H + bb * H + kk]
                : g_c_all[(size_t)(t + 1) * B * H + bb * H + kk - 256];
            As[m][k] = v;
        }
        for (int i = tid; i < 16 * 64; i += 256) {
            int k = i >> 6, n = i & 63;
            Bs[k][n] = g_WsT[(size_t)(k0 + k) * 256 + n0 + n];
        }
        __syncthreads();
        #pragma unroll
        for (int kk = 0; kk < 16; kk++) {
            float a0 = As[ty * 4 + 0][kk], a1 = As[ty * 4 + 1][kk];
            float a2 = As[ty * 4 + 2][kk], a3 = As[ty * 4 + 3][kk];
            float4 b4 = *(const float4*)&Bs[kk][tx * 4];
            acc[0][0] += a0 * b4.x; acc[0][1] += a0 * b4.y; acc[0][2] += a0 * b4.z; acc[0][3] += a0 * b4.w;
            acc[1][0] += a1 * b4.x; acc[1][1] += a1 * b4.y; acc[1][2] += a1 * b4.z; acc[1][3] += a1 * b4.w;
            acc[2][0] += a2 * b4.x; acc[2][1] += a2 * b4.y; acc[2][2] += a2 * b4.z; acc[2][3] += a2 * b4.w;
            acc[3][0] += a3 * b4.x; acc[3][1] += a3 * b4.y; acc[3][2] += a3 * b4.z; acc[3][3] += a3 * b4.w;
        }
        __syncthreads();
    }
    #pragma unroll
    for (int i = 0; i < 4; i++) {
        int r = m0 + ty * 4 + i;
        #pragma unroll
        for (int j = 0; j < 4; j++) {
            int n = n0 + tx * 4 + j;
            g_dec_all[(size_t)r * 256 + n] = ex2((acc[i][j] + bs_[n]) * L2E2);
        }
    }
}

// ---------------- batched e-scores: warp per (b,l), loop t -----------------
__global__ void __launch_bounds__(256)
k_escore_all(const float* __restrict__ v) {
    const int tid = threadIdx.x;
    const int lane = tid & 31, wid = tid >> 5;
    const int gwarp = blockIdx.x * 8 + wid;
    const int b = gwarp >> 11;
    const int l = gwarp & 2047;

    const float4* ef4 = (const float4*)(g_enc_feat + ((size_t)(b * L + l)) * H);
    const float4* v4 = (const float4*)v;
    float4 Ea = ef4[lane * 2], Eb = ef4[lane * 2 + 1];
    float4 va = v4[lane * 2], vb = v4[lane * 2 + 1];
    float Vtot = wreduce(va.x + va.y + va.z + va.w + vb.x + vb.y + vb.z + vb.w);
    float4 w2a = make_float4(2.f * va.x, 2.f * va.y, 2.f * va.z, 2.f * va.w);
    float4 w2b = make_float4(2.f * vb.x, 2.f * vb.y, 2.f * vb.z, 2.f * vb.w);

    float* eout = g_e_tr + ((size_t)(b * L + l)) * 128;

    #pragma unroll 1
    for (int c = 0; c < 4; c++) {
        float ereg = 0.f;
        int tmax = T_STEPS - c * 32;
        if (tmax > 32) tmax = 32;
        #pragma unroll 1
        for (int tt = 0; tt < tmax; tt++) {
            int t = c * 32 + tt;
            const float4* d4 = (const float4*)(g_dec_all + (size_t)(t * B + b) * H);
            float4 Da = d4[lane * 2], Db = d4[lane * 2 + 1];
            float A0 = fmaf(Ea.x, Da.x, 1.f);
            float A1 = fmaf(Ea.y, Da.y, 1.f);
            float A2 = fmaf(Ea.z, Da.z, 1.f);
            float A3 = fmaf(Ea.w, Da.w, 1.f);
            float A4 = fmaf(Eb.x, Db.x, 1.f);
            float A5 = fmaf(Eb.y, Db.y, 1.f);
            float A6 = fmaf(Eb.z, Db.z, 1.f);
            float A7 = fmaf(Eb.w, Db.w, 1.f);
            float acc = w2a.x * rcp(A0);
            acc = fmaf(w2a.y, rcp(A1), acc);
            acc = fmaf(w2a.z, rcp(A2), acc);
            acc = fmaf(w2a.w, rcp(A3), acc);
            acc = fmaf(w2b.x, rcp(A4), acc);
            acc = fmaf(w2b.y, rcp(A5), acc);
            acc = fmaf(w2b.z, rcp(A6), acc);
            acc = fmaf(w2b.w, rcp(A7), acc);
            float s = Vtot - wreduce(acc);
            if (tt == lane) ereg = s;
        }
        if (c * 32 + lane < T_STEPS) eout[c * 32 + lane] = ereg;
    }
}

// ---------------- batched softmax: block per (t,b) -------------------------
__global__ void __launch_bounds__(256)
k_softmax_all(const float* __restrict__ mask, float* __restrict__ o_attn) {
    __shared__ float red[16];
    const int r = blockIdx.x;
    const int t = r >> 4, b = r & 15;
    const int tid = threadIdx.x;
    const int lane = tid & 31, wid = tid >> 5;

    const float* mrow = mask + (size_t)b * L;

    float ev[8], mv[8];
    float mx = -3.4e38f;
    #pragma unroll
    for (int i = 0; i < 8; i++) {
        int l = tid + i * 256;
        ev[i] = g_e_tr[((size_t)(b * L + l)) * 128 + t];
        mv[i] = mrow[l];
        mx = fmaxf(mx, ev[i]);
    }
    mx = wmax(mx);
    if (lane == 0) red[wid] = mx;
    __syncthreads();
    mx = red[0];
    #pragma unroll
    for (int i = 1; i < 8; i++) mx = fmaxf(mx, red[i]);

    float pv[8];
    float s = 0.f;
    #pragma unroll
    for (int i = 0; i < 8; i++) {
        pv[i] = __expf(ev[i] - mx) * mv[i];
        s += pv[i];
    }
    s = wreduce(s);
    if (lane == 0) red[8 + wid] = s;
    __syncthreads();
    s = 0.f;
    #pragma unroll
    for (int i = 0; i < 8; i++) s += red[8 + i];
    float inv = __fdividef(1.f, s);
    #pragma unroll
    for (int i = 0; i < 8; i++)
        o_attn[(size_t)r * L + tid + i * 256] = pv[i] * inv;
}

// ---------------- ctx batched GEMM per b: [128(t),2048]x[2048,512] ---------
__global__ void __launch_bounds__(256)
k_ctx_gemm(const float* __restrict__ enc, const float* __restrict__ o_attn) {
    __shared__ __align__(16) float Ast[16][132];
    __shared__ __align__(16) float Bs[16][64];
    const int tid = threadIdx.x;
    const int b = blockIdx.y;
    const int n0 = blockIdx.x * 64;
    const int tx = tid & 15, ty = tid >> 4;
    unsigned long long acc[4][4];
    #pragma unroll
    for (int p = 0; p < 4; p++)
        #pragma unroll
        for (int n = 0; n < 4; n++) acc[p][n] = 0ull;

    for (int k0 = 0; k0 < L; k0 += 16) {
        __syncthreads();
        #pragma unroll
        for (int u = 0; u < 2; u++) {
            int idx = u * 256 + tid;
            int row = idx >> 2, q = idx & 3;
            float4 f = make_float4(0.f, 0.f, 0.f, 0.f);
            if (row < T_STEPS)
                f = *(const float4*)(o_attn + ((size_t)(row * B + b)) * L + k0 + q * 4);
            Ast[q * 4 + 0][row] = f.x;
            Ast[q * 4 + 1][row] = f.y;
            Ast[q * 4 + 2][row] = f.z;
            Ast[q * 4 + 3][row] = f.w;
        }
        {
            int kk = tid >> 4, n4 = (tid & 15) * 4;
            *(float4*)&Bs[kk][n4] =
                *(const float4*)(enc + ((size_t)(b * L + k0 + kk)) * (2 * H) + n0 + n4);
        }
        __syncthreads();
        #pragma unroll
        for (int kk = 0; kk < 16; kk++) {
            unsigned long long a2[4];
            #pragma unroll
            for (int p = 0; p < 4; p++)
                a2[p] = *(const unsigned long long*)&Ast[kk][ty * 8 + p * 2];
            float4 b4 = *(const float4*)&Bs[kk][tx * 4];
            unsigned long long bb[4];
            bb[0] = pack2(b4.x, b4.x); bb[1] = pack2(b4.y, b4.y);
            bb[2] = pack2(b4.z, b4.z); bb[3] = pack2(b4.w, b4.w);
            #pragma unroll
            for (int p = 0; p < 4; p++)
                #pragma unroll
                for (int n = 0; n < 4; n++)
                    fma2(acc[p][n], a2[p], bb[n]);
        }
    }
    #pragma unroll
    for (int p = 0; p < 4; p++) {
        int t = ty * 8 + p * 2;
        #pragma unroll
        for (int n = 0; n < 4; n++) {
            float2 f = unpack2(acc[p][n]);
            int col = n0 + tx * 4 + n;
            if (t < T_STEPS)
                g_ctx_all[(size_t)(t * B + b) * (2 * H) + col] = f.x;
            if (t + 1 < T_STEPS)
                g_ctx_all[(size_t)((t + 1) * B + b) * (2 * H) + col] = f.y;
        }
    }
}

// ---------------- out batched GEMM: [1600,768]x[768,256] -------------------
__global__ void __launch_bounds__(256)
k_out_gemm(const float* __restrict__ bout, float* __restrict__ o_out) {
    __shared__ float As[64][17];
    __shared__ float Bs[16][64];
    const int m0 = blockIdx.y * 64;
    const int n0 = blockIdx.x * 64;
    const int tid = threadIdx.x;
    const int tx = tid & 15, ty = tid >> 4;
    float acc[4][4] = {};
    for (int k0 = 0; k0 < 768; k0 += 16) {
        for (int i = tid; i < 64 * 16; i += 256) {
            int m = i >> 4, k = i & 15;
            int r = m0 + m;
            int t = r >> 4, bb = r & 15;
            int kk = k0 + k;
            float v = (kk < 256)
                ? g_h_all[(size_t)(t + 1) * B * H + bb * H + kk]
                : g_ctx_all[(size_t)r * 512 + kk - 256];
            As[m][k] = v;
        }
        for (int i = tid; i < 16 * 64; i += 256) {
            int k = i >> 6, n = i & 63;
            Bs[k][n] = g_WoutT[(size_t)(k0 + k) * 256 + n0 + n];
        }
        __syncthreads();
        #pragma unroll
        for (int kk = 0; kk < 16; kk++) {
            float a0 = As[ty * 4 + 0][kk], a1 = As[ty * 4 + 1][kk];
            float a2 = As[ty * 4 + 2][kk], a3 = As[ty * 4 + 3][kk];
            float4 b4 = *(const float4*)&Bs[kk][tx * 4];
            acc[0][0] += a0 * b4.x; acc[0][1] += a0 * b4.y; acc[0][2] += a0 * b4.z; acc[0][3] += a0 * b4.w;
            acc[1][0] += a1 * b4.x; acc[1][1] += a1 * b4.y; acc[1][2] += a1 * b4.z; acc[1][3] += a1 * b4.w;
            acc[2][0] += a2 * b4.x; acc[2][1] += a2 * b4.y; acc[2][2] += a2 * b4.z; acc[2][3] += a2 * b4.w;
            acc[3][0] += a3 * b4.x; acc[3][1] += a3 * b4.y; acc[3][2] += a3 * b4.z; acc[3][3] += a3 * b4.w;
        }
        __syncthreads();
    }
    #pragma unroll
    for (int i = 0; i < 4; i++) {
        int r = m0 + ty * 4 + i;
        #pragma unroll
        for (int j = 0; j < 4; j++) {
            int n = n0 + tx * 4 + j;
            o_out[(size_t)r * 256 + n] = acc[i][j] + bout[n];
        }
    }
}

// ---------------- p_gen batched + h_f/c_f ----------------------------------
__global__ void __launch_bounds__(256)
k_pgen(const float* __restrict__ Wpg, const float* __restrict__ bpg,
       float* __restrict__ o_pgen, float* __restrict__ o_hf, float* __restrict__ o_cf) {
    const int tid = threadIdx.x;
    const int lane = tid & 31, wid = tid >> 5;
    const int blk = blockIdx.x;

    if (blk < 200) {
        const int r = blk * 8 + wid;
        const int t = r >> 4, bb = r & 15;
        float s = 0.f;
        for (int k = lane; k < 4 * H + E; k += 32) {
            float cv;
            if (k < 2 * H) cv = g_ctx_all[(size_t)r * 512 + k];
            else if (k < 3 * H) cv = g_h_all[(size_t)(t + 1) * B * H + bb * H + k - 2 * H];
            else if (k < 4 * H) cv = g_c_all[(size_t)(t + 1) * B * H + bb * H + k - 3 * H];
            else cv = g_x_all[(size_t)r * E + k - 4 * H];
            s += cv * Wpg[k];
        }
        s = wreduce(s);
        if (lane == 0) o_pgen[r] = sig_f(s + bpg[0]);
    } else {
        for (int i = (blk - 200) * 256 + tid; i < B * H; i += 512) {
            o_hf[i] = g_h_all[(size_t)T_STEPS * B * H + i];
            o_cf[i] = g_c_all[(size_t)T_STEPS * B * H + i];
        }
    }
}

// ---------------- host launcher ----------------
extern "C" void kernel_launch(void* const* d_in, const int* in_sizes, int n_in,
                              void* d_out, int out_size) {
    const float* dec_in = (const float*)d_in[0];
    const float* h0     = (const float*)d_in[1];
    const float* c0     = (const float*)d_in[2];
    const float* enc    = (const float*)d_in[3];
    const float* mask   = (const float*)d_in[4];
    const float* Wh     = (const float*)d_in[5];
    const float* bh     = (const float*)d_in[6];
    const float* Ws_    = (const float*)d_in[7];
    const float* bs_    = (const float*)d_in[8];
    const float* v      = (const float*)d_in[9];
    const float* Wx     = (const float*)d_in[10];
    const float* bx     = (const float*)d_in[11];
    const float* Wih    = (const float*)d_in[12];
    const float* bih    = (const float*)d_in[13];
    const float* Whh    = (const float*)d_in[14];
    const float* bhh    = (const float*)d_in[15];
    const float* Wpg    = (const float*)d_in[16];
    const float* bpg    = (const float*)d_in[17];
    const float* Wout   = (const float*)d_in[18];
    const float* bout   = (const float*)d_in[19];

    float* out = (float*)d_out;
    float* o_outputs = out;                                  // [T,B,H]
    float* o_hf = o_outputs + (size_t)T_STEPS * B * H;       // [B,H]
    float* o_cf = o_hf + B * H;                              // [B,H]
    float* o_attn = o_cf + B * H;                            // [T,B,L]
    float* o_pgen = o_attn + (size_t)T_STEPS * B * L;        // [T,B,1]

    // lazy one-time creation (first call is the uncaptured correctness run;
    // no device-memory allocation involved)
    static cudaStream_t s2 = nullptr;
    static cudaEvent_t ev_fork = nullptr, ev_join = nullptr;
    if (s2 == nullptr) {
        cudaStreamCreateWithFlags(&s2, cudaStreamNonBlocking);
        cudaEventCreateWithFlags(&ev_fork, cudaEventDisableTiming);
        cudaEventCreateWithFlags(&ev_join, cudaEventDisableTiming);
    }

    k_prep<<<2384, 256>>>(Wh, Ws_, Wout, Wih, Wx, h0, c0);

    // fork: encfeat on side stream (depends only on prep)
    cudaEventRecord(ev_fork, 0);
    cudaStreamWaitEvent(s2, ev_fork, 0);
    k_encfeat2<<<dim3(4, 256), 256, 0, s2>>>(enc, bh);
    cudaEventRecord(ev_join, s2);

    // main branch: x -> gi -> chain -> dec
    k_xg<<<dim3(2, 25), 256>>>(dec_in, bx);
    k_gig<<<dim3(16, 25), 256>>>(bih, bhh);
    k_chain2<<<64, 512>>>(Whh);
    k_dec_gemm<<<dim3(4, 25), 256>>>(bs_);

    // join: escore needs both enc_feat (s2) and dec_all (main)
    cudaStreamWaitEvent(0, ev_join, 0);

    k_escore_all<<<4096, 256>>>(v);
    k_softmax_all<<<1600, 256>>>(mask, o_attn);
    k_ctx_gemm<<<dim3(8, 16), 256>>>(enc, o_attn);
    k_out_gemm<<<dim3(4, 25), 256>>>(bout, o_outputs);
    k_pgen<<<202, 256>>>(Wpg, bpg, o_pgen, o_hf, o_cf);
}